// round 1
// baseline (speedup 1.0000x reference)
#include <cuda_runtime.h>
#include <math.h>

#define D   256
#define DI  512
#define NH  4
#define DH  128
#define NL  4
#define KC  4
#define NB  8
#define SS  1024
#define NT  (NB*SS)   /* 8192 tokens */
#define NBH (NB*NH)   /* 32 */

// ---------------- scratch (device globals; no allocation) ----------------
__device__ float g_h [NT*D];
__device__ float g_hn[NT*D];
__device__ float g_up[NT*2*DI];
__device__ float g_xc[NT*DI];
__device__ float g_q [NT*DI];
__device__ float g_k [NT*DI];
__device__ float g_v [NT*DI];
__device__ float g_ht[NT*DI];
__device__ float g_mix[NT*DI];
__device__ float g_gates[NT*2*NH];
__device__ float g_alpha[NBH*SS];
__device__ float g_beta [NBH*SS];
__device__ float g_m    [NBH*SS];

// ---------------- embed: h = [x, tf] @ Wp + bp ----------------
__global__ void embed_kernel(const float* __restrict__ x, const float* __restrict__ tf,
                             const float* __restrict__ Wp, const float* __restrict__ bp) {
    int t = blockIdx.x, d = threadIdx.x;
    float acc = bp[d] + x[t] * Wp[d];
#pragma unroll
    for (int j = 0; j < 4; j++) acc += tf[t*4 + j] * Wp[(1+j)*D + d];
    g_h[t*D + d] = acc;
}

// ---------------- LayerNorm over D=256, one block per token ----------------
__global__ void ln256_kernel(const float* __restrict__ in, const float* __restrict__ g,
                             const float* __restrict__ b, float* __restrict__ out) {
    int t = blockIdx.x, tid = threadIdx.x;
    __shared__ float red[256];
    float v = in[t*256 + tid];
    red[tid] = v; __syncthreads();
    for (int off = 128; off > 0; off >>= 1) { if (tid < off) red[tid] += red[tid+off]; __syncthreads(); }
    float mean = red[0] * (1.f/256.f); __syncthreads();
    float c = v - mean;
    red[tid] = c*c; __syncthreads();
    for (int off = 128; off > 0; off >>= 1) { if (tid < off) red[tid] += red[tid+off]; __syncthreads(); }
    float var = red[0] * (1.f/256.f);
    out[t*256 + tid] = c * rsqrtf(var + 1e-5f) * g[tid] + b[tid];
}

// ---------------- generic tiled fp32 GEMM: C = A(MxK)@B(KxN) + bias + resid ----------------
template<int BM, int BN, int BK, int TM, int TN>
__global__ void gemm_kernel(const float* __restrict__ A, int lda,
                            const float* __restrict__ Bw, int ldb,
                            const float* __restrict__ bias,
                            const float* __restrict__ resid,
                            float* __restrict__ C, int ldc, int K) {
    constexpr int THREADS = (BM*BN)/(TM*TN);
    __shared__ float As[BK][BM];
    __shared__ float Bs[BK][BN];
    int tid = threadIdx.x;
    int tx = tid % (BN/TN);
    int ty = tid / (BN/TN);
    int rowBase = blockIdx.x * BM;
    int colBase = blockIdx.y * BN;
    float acc[TM][TN];
#pragma unroll
    for (int m = 0; m < TM; m++)
#pragma unroll
        for (int n = 0; n < TN; n++) acc[m][n] = 0.f;

    constexpr int A4 = BM*BK/4;
    constexpr int B4 = BK*BN/4;
    for (int k0 = 0; k0 < K; k0 += BK) {
#pragma unroll
        for (int i = tid; i < A4; i += THREADS) {
            int r  = i / (BK/4);
            int c4 = i % (BK/4);
            float4 v = *(const float4*)(A + (size_t)(rowBase + r)*lda + k0 + c4*4);
            As[c4*4+0][r] = v.x; As[c4*4+1][r] = v.y; As[c4*4+2][r] = v.z; As[c4*4+3][r] = v.w;
        }
#pragma unroll
        for (int i = tid; i < B4; i += THREADS) {
            int r  = i / (BN/4);
            int c4 = i % (BN/4);
            *(float4*)(&Bs[r][c4*4]) = *(const float4*)(Bw + (size_t)(k0 + r)*ldb + colBase + c4*4);
        }
        __syncthreads();
#pragma unroll
        for (int kk = 0; kk < BK; kk++) {
            float a[TM], bb[TN];
#pragma unroll
            for (int m = 0; m < TM; m++) a[m] = As[kk][ty*TM + m];
#pragma unroll
            for (int n = 0; n < TN; n++) bb[n] = Bs[kk][tx*TN + n];
#pragma unroll
            for (int m = 0; m < TM; m++)
#pragma unroll
                for (int n = 0; n < TN; n++) acc[m][n] += a[m]*bb[n];
        }
        __syncthreads();
    }
#pragma unroll
    for (int m = 0; m < TM; m++) {
        int row = rowBase + ty*TM + m;
#pragma unroll
        for (int n = 0; n < TN; n++) {
            int col = colBase + tx*TN + n;
            float v = acc[m][n];
            if (bias)  v += bias[col];
            if (resid) v += resid[(size_t)row*ldc + col];
            C[(size_t)row*ldc + col] = v;
        }
    }
}

// ---------------- causal depthwise conv (K=4) + SiLU ----------------
__global__ void conv_kernel(const float* __restrict__ w, const float* __restrict__ bias) {
    int idx = blockIdx.x * blockDim.x + threadIdx.x;   // NT*DI
    int c = idx % DI;
    int t = idx / DI;
    int s = t % SS;
    float acc = bias[c];
#pragma unroll
    for (int j = 0; j < KC; j++) {
        int ss = s - 3 + j;
        if (ss >= 0) acc += g_up[(size_t)(t - 3 + j)*2*DI + c] * w[j*DI + c];
    }
    g_xc[idx] = acc / (1.f + __expf(-acc));
}

// ---------------- gate projection: gates = [q,k,v] @ Wif + bif ----------------
__global__ void gates_kernel(const float* __restrict__ Wif, const float* __restrict__ bif) {
    int t = blockIdx.x, tid = threadIdx.x;
    __shared__ float red[256*8];
    float p[8];
#pragma unroll
    for (int g8 = 0; g8 < 8; g8++) p[g8] = 0.f;
    for (int i = tid; i < 3*DI; i += 256) {
        float val = (i < DI) ? g_q[(size_t)t*DI + i]
                  : (i < 2*DI) ? g_k[(size_t)t*DI + i - DI]
                               : g_v[(size_t)t*DI + i - 2*DI];
        const float* wr = Wif + i*8;
#pragma unroll
        for (int g8 = 0; g8 < 8; g8++) p[g8] += val * wr[g8];
    }
#pragma unroll
    for (int g8 = 0; g8 < 8; g8++) red[tid*8 + g8] = p[g8];
    __syncthreads();
    for (int off = 128; off > 0; off >>= 1) {
        if (tid < off) {
#pragma unroll
            for (int g8 = 0; g8 < 8; g8++) red[tid*8 + g8] += red[(tid+off)*8 + g8];
        }
        __syncthreads();
    }
    if (tid < 8) g_gates[t*8 + tid] = red[tid] + bif[tid];
}

// ---------------- gate scan: F cumsum, beta, alpha=-runmax, m ----------------
__global__ void gatescan_kernel() {
    int bh = threadIdx.x;
    if (bh >= NBH) return;
    int b = bh >> 2, h = bh & 3;
    float F = 0.f, rmax = -1e30f;
    for (int t = 0; t < SS; t++) {
        const float* gp = g_gates + (size_t)(b*SS + t)*8;
        float fp = gp[NH + h], ipv = gp[h];
        float lf = (fp >= 0.f) ? -log1pf(expf(-fp)) : fp - log1pf(expf(fp));
        F += lf;
        float bt = ipv - F;
        rmax = fmaxf(rmax, bt);
        g_beta [bh*SS + t] = bt;
        g_alpha[bh*SS + t] = -rmax;
        g_m    [bh*SS + t] = F + rmax;
    }
}

// ---------------- mLSTM attention: per (bh, q-tile of 64), s-tiles of 32 ----------------
#define ATTN_STR  132
#define ATTN_PSTR 33
#define ATTN_SMEM ((64*ATTN_STR + 32*ATTN_STR + 32*ATTN_STR + 64*ATTN_PSTR + 64 + 64 + 32 + 64)*4)

__global__ void attn_kernel() {
    extern __shared__ float sm[];
    float* Qs = sm;                       // 64 x 132
    float* Ks = Qs + 64*ATTN_STR;         // 32 x 132
    float* Vs = Ks + 32*ATTN_STR;         // 32 x 132
    float* Ps = Vs + 32*ATTN_STR;         // 64 x 33
    float* al = Ps + 64*ATTN_PSTR;        // 64
    float* me = al + 64;                  // 64
    float* bt = me + 64;                  // 32
    float* rsum = bt + 32;                // 64

    int qt = blockIdx.x, bh = blockIdx.y;
    int b = bh >> 2, h = bh & 3;
    int tid = threadIdx.x;
    int t0 = qt * 64;

    // load Q tile
#pragma unroll
    for (int r8 = 0; r8 < 8; r8++) {
        int idx = tid + r8*256;           // 0..2047
        int row = idx >> 5, c4 = (idx & 31)*4;
        float4 val = *(const float4*)(g_q + (size_t)(b*SS + t0 + row)*DI + h*DH + c4);
        *(float4*)(Qs + row*ATTN_STR + c4) = val;
    }
    if (tid < 64) {
        al[tid] = g_alpha[bh*SS + t0 + tid];
        me[tid] = __expf(-g_m[bh*SS + t0 + tid]);
    }

    float out[32];
#pragma unroll
    for (int i = 0; i < 32; i++) out[i] = 0.f;
    int qi = tid >> 2, qd = tid & 3;
    float rs = 0.f;
    int nst = 2*qt + 2;

    for (int st = 0; st < nst; st++) {
        int s0 = st * 32;
        __syncthreads();
#pragma unroll
        for (int r4 = 0; r4 < 4; r4++) {
            int idx = tid + r4*256;       // 0..1023
            int row = idx >> 5, c4 = (idx & 31)*4;
            *(float4*)(Ks + row*ATTN_STR + c4) = *(const float4*)(g_k + (size_t)(b*SS + s0 + row)*DI + h*DH + c4);
            *(float4*)(Vs + row*ATTN_STR + c4) = *(const float4*)(g_v + (size_t)(b*SS + s0 + row)*DI + h*DH + c4);
        }
        if (tid < 32) bt[tid] = g_beta[bh*SS + s0 + tid];
        __syncthreads();

        // score phase: thread -> row qi, cols j0..j0+7
        float pacc[8];
#pragma unroll
        for (int jj = 0; jj < 8; jj++) pacc[jj] = 0.f;
        int j0 = qd * 8;
        for (int kk = 0; kk < DH; kk += 4) {
            float4 qv = *(const float4*)(Qs + qi*ATTN_STR + kk);
#pragma unroll
            for (int jj = 0; jj < 8; jj++) {
                float4 kv = *(const float4*)(Ks + (j0+jj)*ATTN_STR + kk);
                pacc[jj] += qv.x*kv.x + qv.y*kv.y + qv.z*kv.z + qv.w*kv.w;
            }
        }
        int tg = t0 + qi;
#pragma unroll
        for (int jj = 0; jj < 8; jj++) {
            int sg = s0 + j0 + jj;
            float w = (sg <= tg) ? __expf(al[qi] + bt[j0+jj]) : 0.f;
            Ps[qi*ATTN_PSTR + j0 + jj] = pacc[jj] * 0.08838834764831845f * w;
        }
        __syncthreads();

        // AV phase: thread -> row qi, cols {qd*4 + w8*16 + 0..3}
#pragma unroll 4
        for (int j = 0; j < 32; j++) {
            float p = Ps[qi*ATTN_PSTR + j];
            if (qd == 0) rs += p;
            const float* vrow = Vs + j*ATTN_STR;
#pragma unroll
            for (int w8 = 0; w8 < 8; w8++) {
                float4 vv = *(const float4*)(vrow + qd*4 + w8*16);
                out[w8*4+0] += p*vv.x; out[w8*4+1] += p*vv.y;
                out[w8*4+2] += p*vv.z; out[w8*4+3] += p*vv.w;
            }
        }
    }
    __syncthreads();
    if (qd == 0) rsum[qi] = rs;
    __syncthreads();
    float norm = fmaxf(fabsf(rsum[qi]), me[qi]) + 1e-6f;
    float inv = 1.f / norm;
    float* obase = g_ht + (size_t)(b*SS + t0 + qi)*DI + h*DH;
#pragma unroll
    for (int w8 = 0; w8 < 8; w8++) {
        float4 o;
        o.x = out[w8*4+0]*inv; o.y = out[w8*4+1]*inv;
        o.z = out[w8*4+2]*inv; o.w = out[w8*4+3]*inv;
        *(float4*)(obase + qd*4 + w8*16) = o;
    }
}

// ---------------- per-head LN + skip + SiLU(z) gate ----------------
__global__ void gnmerge_kernel(const float* __restrict__ gn_g, const float* __restrict__ gn_b,
                               const float* __restrict__ skip) {
    int t = blockIdx.x, tid = threadIdx.x;   // 512 threads
    __shared__ float red[512];
    int l = tid & 127;
    int gbase = (tid >> 7) << 7;
    float v = g_ht[(size_t)t*DI + tid];
    red[tid] = v; __syncthreads();
    for (int off = 64; off > 0; off >>= 1) { if (l < off) red[tid] += red[tid+off]; __syncthreads(); }
    float mean = red[gbase] * (1.f/128.f); __syncthreads();
    float c = v - mean;
    red[tid] = c*c; __syncthreads();
    for (int off = 64; off > 0; off >>= 1) { if (l < off) red[tid] += red[tid+off]; __syncthreads(); }
    float var = red[gbase] * (1.f/128.f);
    float y = c * rsqrtf(var + 1e-5f) * gn_g[tid] + gn_b[tid];
    y += skip[tid] * g_xc[(size_t)t*DI + tid];
    float z = g_up[(size_t)t*2*DI + DI + tid];
    y *= z / (1.f + __expf(-z));
    g_mix[(size_t)t*DI + tid] = y;
}

// ---------------- final LN on last token + Wf projection ----------------
__global__ void final_kernel(const float* __restrict__ lnf_g, const float* __restrict__ lnf_b,
                             const float* __restrict__ Wf, const float* __restrict__ bf,
                             float* __restrict__ out) {
    int b = blockIdx.x, tid = threadIdx.x;
    __shared__ float red[256];
    float v = g_h[(size_t)(b*SS + SS - 1)*D + tid];
    red[tid] = v; __syncthreads();
    for (int off = 128; off > 0; off >>= 1) { if (tid < off) red[tid] += red[tid+off]; __syncthreads(); }
    float mean = red[0] * (1.f/256.f); __syncthreads();
    float c = v - mean;
    red[tid] = c*c; __syncthreads();
    for (int off = 128; off > 0; off >>= 1) { if (tid < off) red[tid] += red[tid+off]; __syncthreads(); }
    float var = red[0] * (1.f/256.f); __syncthreads();
    float y = c * rsqrtf(var + 1e-5f) * lnf_g[tid] + lnf_b[tid];
    red[tid] = y * Wf[tid]; __syncthreads();
    for (int off = 128; off > 0; off >>= 1) { if (tid < off) red[tid] += red[tid+off]; __syncthreads(); }
    if (tid == 0) out[b] = red[0] + bf[0];
}

// ---------------- host ----------------
static float* symaddr(const void* sym) {
    void* p = nullptr;
    cudaGetSymbolAddress(&p, sym);
    return (float*)p;
}

extern "C" void kernel_launch(void* const* d_in, const int* in_sizes, int n_in,
                              void* d_out, int out_size) {
    const float* x      = (const float*)d_in[0];
    const float* tf     = (const float*)d_in[1];
    const float* Wp     = (const float*)d_in[2];
    const float* bp     = (const float*)d_in[3];
    const float* ln_g   = (const float*)d_in[4];
    const float* ln_b   = (const float*)d_in[5];
    const float* Wup    = (const float*)d_in[6];
    const float* bup    = (const float*)d_in[7];
    const float* conv_w = (const float*)d_in[8];
    const float* conv_b = (const float*)d_in[9];
    const float* Wq     = (const float*)d_in[10];
    const float* Wk     = (const float*)d_in[11];
    const float* Wv     = (const float*)d_in[12];
    const float* Wif    = (const float*)d_in[13];
    const float* bif    = (const float*)d_in[14];
    const float* gn_g   = (const float*)d_in[15];
    const float* gn_b   = (const float*)d_in[16];
    const float* skip   = (const float*)d_in[17];
    const float* Wdown  = (const float*)d_in[18];
    const float* bdown  = (const float*)d_in[19];
    const float* lnf_g  = (const float*)d_in[20];
    const float* lnf_b  = (const float*)d_in[21];
    const float* Wf     = (const float*)d_in[22];
    const float* bf     = (const float*)d_in[23];
    float* out = (float*)d_out;

    float* p_h   = symaddr(g_h);
    float* p_hn  = symaddr(g_hn);
    float* p_up  = symaddr(g_up);
    float* p_xc  = symaddr(g_xc);
    float* p_q   = symaddr(g_q);
    float* p_k   = symaddr(g_k);
    float* p_v   = symaddr(g_v);
    float* p_mix = symaddr(g_mix);

    cudaFuncSetAttribute(attn_kernel, cudaFuncAttributeMaxDynamicSharedMemorySize, ATTN_SMEM);

    embed_kernel<<<NT, 256>>>(x, tf, Wp, bp);

    for (int l = 0; l < NL; l++) {
        ln256_kernel<<<NT, 256>>>(p_h, ln_g + l*D, ln_b + l*D, p_hn);

        // up: (8192x256)@(256x1024)+bup
        gemm_kernel<128,128,16,8,8><<<dim3(NT/128, 1024/128), 256>>>(
            p_hn, D, Wup + (size_t)l*D*2*DI, 2*DI, bup + l*2*DI, nullptr, p_up, 2*DI, D);

        conv_kernel<<<NT*DI/256, 256>>>(conv_w + l*KC*DI, conv_b + l*DI);

        // q,k from xc ; v from xm (first half of up rows, lda=1024)
        gemm_kernel<128,128,16,8,8><<<dim3(NT/128, DI/128), 256>>>(
            p_xc, DI, Wq + (size_t)l*DI*DI, DI, nullptr, nullptr, p_q, DI, DI);
        gemm_kernel<128,128,16,8,8><<<dim3(NT/128, DI/128), 256>>>(
            p_xc, DI, Wk + (size_t)l*DI*DI, DI, nullptr, nullptr, p_k, DI, DI);
        gemm_kernel<128,128,16,8,8><<<dim3(NT/128, DI/128), 256>>>(
            p_up, 2*DI, Wv + (size_t)l*DI*DI, DI, nullptr, nullptr, p_v, DI, DI);

        gates_kernel<<<NT, 256>>>(Wif + (size_t)l*3*DI*2*NH, bif + l*2*NH);
        gatescan_kernel<<<1, 32>>>();

        attn_kernel<<<dim3(SS/64, NBH), 256, ATTN_SMEM>>>();

        gnmerge_kernel<<<NT, 512>>>(gn_g + l*DI, gn_b + l*DI, skip + l*DI);

        // down: (8192x512)@(512x256)+bdown+residual(h) -> h
        gemm_kernel<64,64,16,4,4><<<dim3(NT/64, D/64), 256>>>(
            p_mix, DI, Wdown + (size_t)l*DI*D, D, bdown + l*D, p_h, p_h, D, DI);
    }

    final_kernel<<<NB, 256>>>(lnf_g, lnf_b, Wf, bf, out);
}

// round 3
// speedup vs baseline: 1.1338x; 1.1338x over previous
#include <cuda_runtime.h>
#include <cuda_bf16.h>
#include <math.h>
#include <stdint.h>

#define D   256
#define DI  512
#define NH  4
#define DH  128
#define NL  4
#define KC  4
#define NB  8
#define SS  1024
#define NT  (NB*SS)   /* 8192 tokens */
#define NBH (NB*NH)   /* 32 */

// ---------------- scratch (device globals; no allocation) ----------------
__device__ float g_h [NT*D];
__device__ float g_up[NT*2*DI];
__device__ float g_xc[NT*DI];
__device__ float g_q [NT*DI];
__device__ float g_k [NT*DI];
__device__ float g_v [NT*DI];
__device__ float g_ht[NT*DI];
__device__ float g_gates[NT*2*NH];
__device__ float g_alpha[NBH*SS];
__device__ float g_beta [NBH*SS];
__device__ float g_m    [NBH*SS];

// bf16 hi/lo split activations
__device__ __nv_bfloat16 g_hn_h[NT*D],  g_hn_l[NT*D];
__device__ __nv_bfloat16 g_xc_h[NT*DI], g_xc_l[NT*DI];
__device__ __nv_bfloat16 g_xm_h[NT*DI], g_xm_l[NT*DI];
__device__ __nv_bfloat16 g_mix_h[NT*DI], g_mix_l[NT*DI];

// bf16 hi/lo transposed weights [N,K] per layer
#define WT_UP_OFF   0
#define WT_Q_OFF    262144
#define WT_K_OFF    524288
#define WT_V_OFF    786432
#define WT_DN_OFF   1048576
#define WT_L        1179648
__device__ __nv_bfloat16 g_wt_h[NL*WT_L], g_wt_l[NL*WT_L];

__device__ __forceinline__ uint32_t smem_u32(const void* p) {
    uint32_t a;
    asm("{ .reg .u64 t; cvta.to.shared.u64 t, %1; cvt.u32.u64 %0, t; }" : "=r"(a) : "l"(p));
    return a;
}
__device__ __forceinline__ void ldmx4(uint32_t* r, uint32_t addr) {
    asm volatile("ldmatrix.sync.aligned.m8n8.x4.shared.b16 {%0,%1,%2,%3}, [%4];"
        : "=r"(r[0]), "=r"(r[1]), "=r"(r[2]), "=r"(r[3]) : "r"(addr));
}
__device__ __forceinline__ void mma16816(float* d, const uint32_t* a, const uint32_t* b) {
    asm volatile(
        "mma.sync.aligned.m16n8k16.row.col.f32.bf16.bf16.f32 "
        "{%0,%1,%2,%3}, {%4,%5,%6,%7}, {%8,%9}, {%0,%1,%2,%3};"
        : "+f"(d[0]), "+f"(d[1]), "+f"(d[2]), "+f"(d[3])
        : "r"(a[0]), "r"(a[1]), "r"(a[2]), "r"(a[3]), "r"(b[0]), "r"(b[1]));
}

// ---------------- embed ----------------
__global__ void embed_kernel(const float* __restrict__ x, const float* __restrict__ tf,
                             const float* __restrict__ Wp, const float* __restrict__ bp) {
    int t = blockIdx.x, d = threadIdx.x;
    float acc = bp[d] + x[t] * Wp[d];
#pragma unroll
    for (int j = 0; j < 4; j++) acc += tf[t*4 + j] * Wp[(1+j)*D + d];
    g_h[t*D + d] = acc;
}

// ---------------- LayerNorm over D=256 -> bf16 hi/lo ----------------
__global__ void ln256_kernel(const float* __restrict__ in, const float* __restrict__ g,
                             const float* __restrict__ b) {
    int t = blockIdx.x, tid = threadIdx.x;
    __shared__ float red[256];
    float v = in[t*256 + tid];
    red[tid] = v; __syncthreads();
    for (int off = 128; off > 0; off >>= 1) { if (tid < off) red[tid] += red[tid+off]; __syncthreads(); }
    float mean = red[0] * (1.f/256.f); __syncthreads();
    float c = v - mean;
    red[tid] = c*c; __syncthreads();
    for (int off = 128; off > 0; off >>= 1) { if (tid < off) red[tid] += red[tid+off]; __syncthreads(); }
    float var = red[0] * (1.f/256.f);
    float y = c * rsqrtf(var + 1e-5f) * g[tid] + b[tid];
    __nv_bfloat16 h = __float2bfloat16(y);
    g_hn_h[t*256 + tid] = h;
    g_hn_l[t*256 + tid] = __float2bfloat16(y - __bfloat162float(h));
}

// ---------------- weight transpose + split: W (KxN) -> Wt hi/lo (NxK) ----------------
__global__ void wsplit_kernel(const float* __restrict__ W, int K, int N,
                              __nv_bfloat16* __restrict__ th, __nv_bfloat16* __restrict__ tl) {
    __shared__ float tile[32][33];
    int k0 = blockIdx.x*32, n0 = blockIdx.y*32;
    int tx = threadIdx.x, ty = threadIdx.y;
    for (int i = ty; i < 32; i += 8)
        tile[i][tx] = W[(size_t)(k0+i)*N + n0 + tx];
    __syncthreads();
    for (int i = ty; i < 32; i += 8) {
        float v = tile[tx][i];
        __nv_bfloat16 h = __float2bfloat16(v);
        size_t o = (size_t)(n0+i)*K + k0 + tx;
        th[o] = h;
        tl[o] = __float2bfloat16(v - __bfloat162float(h));
    }
}

// ---------------- activation split ----------------
__global__ void split_kernel(const float* __restrict__ src, int srcld, int cols,
                             __nv_bfloat16* __restrict__ hi, __nv_bfloat16* __restrict__ lo) {
    int idx = blockIdx.x * blockDim.x + threadIdx.x;
    int t = idx / cols, c = idx - t*cols;
    float v = src[(size_t)t*srcld + c];
    __nv_bfloat16 h = __float2bfloat16(v);
    hi[idx] = h;
    lo[idx] = __float2bfloat16(v - __bfloat162float(h));
}

// ================= mma.sync split-bf16 GEMM =================
// C(M x N) = (Ah+Al)(M x K) @ (Bh+Bl)^T,  B stored [N,K].
// CTA tile 128x128, K-chunk 32. 8 warps: 4(m) x 2(n), warp tile 32x64.
#define TSTR 40   /* bf16 elements per smem row (80B, ldmatrix conflict-free) */

__global__ void __launch_bounds__(256, 1)
mmagemm_kernel(const __nv_bfloat16* __restrict__ Ah, const __nv_bfloat16* __restrict__ Al, int lda,
               const __nv_bfloat16* __restrict__ Bh, const __nv_bfloat16* __restrict__ Bl,
               const float* __restrict__ bias, const float* __restrict__ resid,
               float* __restrict__ C, int ldc, int K) {
    __shared__ __align__(16) __nv_bfloat16 sAh[128*TSTR];
    __shared__ __align__(16) __nv_bfloat16 sAl[128*TSTR];
    __shared__ __align__(16) __nv_bfloat16 sBh[128*TSTR];
    __shared__ __align__(16) __nv_bfloat16 sBl[128*TSTR];

    int tid = threadIdx.x;
    int warp = tid >> 5, lane = tid & 31;
    int wm = warp >> 1, wn = warp & 1;
    int rowBase = blockIdx.x * 128;
    int colBase = blockIdx.y * 128;

    const __nv_bfloat16* Ah0 = Ah + (size_t)rowBase*lda;
    const __nv_bfloat16* Al0 = Al + (size_t)rowBase*lda;
    const __nv_bfloat16* Bh0 = Bh + (size_t)colBase*K;
    const __nv_bfloat16* Bl0 = Bl + (size_t)colBase*K;

    float acc[2][8][4];
#pragma unroll
    for (int mt = 0; mt < 2; mt++)
#pragma unroll
        for (int nt = 0; nt < 8; nt++)
#pragma unroll
            for (int i = 0; i < 4; i++) acc[mt][nt][i] = 0.f;

    // per-thread ldmatrix byte offsets
    uint32_t aoff[2][2], boff[4][2];
#pragma unroll
    for (int mt = 0; mt < 2; mt++)
#pragma unroll
        for (int ks = 0; ks < 2; ks++)
            aoff[mt][ks] = ((wm*32 + mt*16 + (lane & 15))*TSTR + ks*16 + ((lane >> 4) << 3))*2;
#pragma unroll
    for (int ntp = 0; ntp < 4; ntp++)
#pragma unroll
        for (int ks = 0; ks < 2; ks++)
            boff[ntp][ks] = ((wn*64 + ntp*16 + ((lane >> 4) << 3) + (lane & 7))*TSTR
                             + ks*16 + (((lane >> 3) & 1) << 3))*2;

    uint32_t sAh_b = smem_u32(sAh), sAl_b = smem_u32(sAl);
    uint32_t sBh_b = smem_u32(sBh), sBl_b = smem_u32(sBl);

    int nch = K >> 5;
    for (int ch = 0; ch < nch; ch++) {
        int k0 = ch << 5;
        __syncthreads();
        // load 4 tiles: 128 rows x 32 bf16 each; 512 uint4 per tile
#pragma unroll
        for (int j = 0; j < 2; j++) {
            int i = tid + j*256;
            int row = i >> 2, quad = i & 3;
            size_t go = (size_t)row*lda + k0 + quad*8;
            uint32_t so = (row*TSTR + quad*8)*2;
            *(uint4*)((char*)sAh + so) = *(const uint4*)(Ah0 + go);
            *(uint4*)((char*)sAl + so) = *(const uint4*)(Al0 + go);
            size_t gb = (size_t)row*K + k0 + quad*8;
            *(uint4*)((char*)sBh + so) = *(const uint4*)(Bh0 + gb);
            *(uint4*)((char*)sBl + so) = *(const uint4*)(Bl0 + gb);
        }
        __syncthreads();

#pragma unroll
        for (int ks = 0; ks < 2; ks++) {
            uint32_t ah[2][4], al[2][4], bh[4][4], bl[4][4];
#pragma unroll
            for (int mt = 0; mt < 2; mt++) {
                ldmx4(ah[mt], sAh_b + aoff[mt][ks]);
                ldmx4(al[mt], sAl_b + aoff[mt][ks]);
            }
#pragma unroll
            for (int ntp = 0; ntp < 4; ntp++) {
                ldmx4(bh[ntp], sBh_b + boff[ntp][ks]);
                ldmx4(bl[ntp], sBl_b + boff[ntp][ks]);
            }
#pragma unroll
            for (int mt = 0; mt < 2; mt++)
#pragma unroll
                for (int nt = 0; nt < 8; nt++) {
                    int p = nt >> 1, hh = (nt & 1) * 2;
                    mma16816(acc[mt][nt], ah[mt], &bh[p][hh]);
                    mma16816(acc[mt][nt], al[mt], &bh[p][hh]);
                    mma16816(acc[mt][nt], ah[mt], &bl[p][hh]);
                }
        }
    }

    // epilogue
    int r0b = rowBase + wm*32 + (lane >> 2);
    int cb  = colBase + wn*64 + (lane & 3)*2;
#pragma unroll
    for (int mt = 0; mt < 2; mt++) {
#pragma unroll
        for (int nt = 0; nt < 8; nt++) {
            int col = cb + nt*8;
#pragma unroll
            for (int half = 0; half < 2; half++) {
                int row = r0b + mt*16 + half*8;
                float vx = acc[mt][nt][half*2+0];
                float vy = acc[mt][nt][half*2+1];
                if (bias) { vx += bias[col]; vy += bias[col+1]; }
                if (resid) {
                    const float2 r2 = *(const float2*)(resid + (size_t)row*ldc + col);
                    vx += r2.x; vy += r2.y;
                }
                float2 o; o.x = vx; o.y = vy;
                *(float2*)(C + (size_t)row*ldc + col) = o;
            }
        }
    }
}

// ---------------- causal depthwise conv (K=4) + SiLU -> fp32 + hi/lo ----------------
__global__ void conv_kernel(const float* __restrict__ w, const float* __restrict__ bias) {
    int idx = blockIdx.x * blockDim.x + threadIdx.x;
    int c = idx % DI;
    int t = idx / DI;
    int s = t % SS;
    float acc = bias[c];
#pragma unroll
    for (int j = 0; j < KC; j++) {
        int ss = s - 3 + j;
        if (ss >= 0) acc += g_up[(size_t)(t - 3 + j)*2*DI + c] * w[j*DI + c];
    }
    float y = acc / (1.f + __expf(-acc));
    g_xc[idx] = y;
    __nv_bfloat16 h = __float2bfloat16(y);
    g_xc_h[idx] = h;
    g_xc_l[idx] = __float2bfloat16(y - __bfloat162float(h));
}

// ---------------- gate projection ----------------
__global__ void gates_kernel(const float* __restrict__ Wif, const float* __restrict__ bif) {
    int t = blockIdx.x, tid = threadIdx.x;
    __shared__ float red[256*8];
    float p[8];
#pragma unroll
    for (int g8 = 0; g8 < 8; g8++) p[g8] = 0.f;
    for (int i = tid; i < 3*DI; i += 256) {
        float val = (i < DI) ? g_q[(size_t)t*DI + i]
                  : (i < 2*DI) ? g_k[(size_t)t*DI + i - DI]
                               : g_v[(size_t)t*DI + i - 2*DI];
        const float* wr = Wif + i*8;
#pragma unroll
        for (int g8 = 0; g8 < 8; g8++) p[g8] += val * wr[g8];
    }
#pragma unroll
    for (int g8 = 0; g8 < 8; g8++) red[tid*8 + g8] = p[g8];
    __syncthreads();
    for (int off = 128; off > 0; off >>= 1) {
        if (tid < off) {
#pragma unroll
            for (int g8 = 0; g8 < 8; g8++) red[tid*8 + g8] += red[(tid+off)*8 + g8];
        }
        __syncthreads();
    }
    if (tid < 8) g_gates[t*8 + tid] = red[tid] + bif[tid];
}

// ---------------- gate scan ----------------
__global__ void gatescan_kernel() {
    int bh = threadIdx.x;
    if (bh >= NBH) return;
    int b = bh >> 2, h = bh & 3;
    float F = 0.f, rmax = -1e30f;
    for (int t = 0; t < SS; t++) {
        const float* gp = g_gates + (size_t)(b*SS + t)*8;
        float fp = gp[NH + h], ipv = gp[h];
        float lf = (fp >= 0.f) ? -log1pf(expf(-fp)) : fp - log1pf(expf(fp));
        F += lf;
        float bt = ipv - F;
        rmax = fmaxf(rmax, bt);
        g_beta [bh*SS + t] = bt;
        g_alpha[bh*SS + t] = -rmax;
        g_m    [bh*SS + t] = F + rmax;
    }
}

// ---------------- mLSTM attention (scalar fp32) ----------------
#define ATTN_STR  132
#define ATTN_PSTR 33
#define ATTN_SMEM ((64*ATTN_STR + 32*ATTN_STR + 32*ATTN_STR + 64*ATTN_PSTR + 64 + 64 + 32 + 64)*4)

__global__ void attn_kernel() {
    extern __shared__ float sm[];
    float* Qs = sm;
    float* Ks = Qs + 64*ATTN_STR;
    float* Vs = Ks + 32*ATTN_STR;
    float* Ps = Vs + 32*ATTN_STR;
    float* al = Ps + 64*ATTN_PSTR;
    float* me = al + 64;
    float* bt = me + 64;
    float* rsum = bt + 32;

    int qt = blockIdx.x, bh = blockIdx.y;
    int b = bh >> 2, h = bh & 3;
    int tid = threadIdx.x;
    int t0 = qt * 64;

#pragma unroll
    for (int r8 = 0; r8 < 8; r8++) {
        int idx = tid + r8*256;
        int row = idx >> 5, c4 = (idx & 31)*4;
        float4 val = *(const float4*)(g_q + (size_t)(b*SS + t0 + row)*DI + h*DH + c4);
        *(float4*)(Qs + row*ATTN_STR + c4) = val;
    }
    if (tid < 64) {
        al[tid] = g_alpha[bh*SS + t0 + tid];
        me[tid] = __expf(-g_m[bh*SS + t0 + tid]);
    }

    float out[32];
#pragma unroll
    for (int i = 0; i < 32; i++) out[i] = 0.f;
    int qi = tid >> 2, qd = tid & 3;
    float rs = 0.f;
    int nst = 2*qt + 2;

    for (int st = 0; st < nst; st++) {
        int s0 = st * 32;
        __syncthreads();
#pragma unroll
        for (int r4 = 0; r4 < 4; r4++) {
            int idx = tid + r4*256;
            int row = idx >> 5, c4 = (idx & 31)*4;
            *(float4*)(Ks + row*ATTN_STR + c4) = *(const float4*)(g_k + (size_t)(b*SS + s0 + row)*DI + h*DH + c4);
            *(float4*)(Vs + row*ATTN_STR + c4) = *(const float4*)(g_v + (size_t)(b*SS + s0 + row)*DI + h*DH + c4);
        }
        if (tid < 32) bt[tid] = g_beta[bh*SS + s0 + tid];
        __syncthreads();

        float pacc[8];
#pragma unroll
        for (int jj = 0; jj < 8; jj++) pacc[jj] = 0.f;
        int j0 = qd * 8;
        for (int kk = 0; kk < DH; kk += 4) {
            float4 qv = *(const float4*)(Qs + qi*ATTN_STR + kk);
#pragma unroll
            for (int jj = 0; jj < 8; jj++) {
                float4 kv = *(const float4*)(Ks + (j0+jj)*ATTN_STR + kk);
                pacc[jj] += qv.x*kv.x + qv.y*kv.y + qv.z*kv.z + qv.w*kv.w;
            }
        }
        int tg = t0 + qi;
#pragma unroll
        for (int jj = 0; jj < 8; jj++) {
            int sg = s0 + j0 + jj;
            float w = (sg <= tg) ? __expf(al[qi] + bt[j0+jj]) : 0.f;
            Ps[qi*ATTN_PSTR + j0 + jj] = pacc[jj] * 0.08838834764831845f * w;
        }
        __syncthreads();

#pragma unroll 4
        for (int j = 0; j < 32; j++) {
            float p = Ps[qi*ATTN_PSTR + j];
            if (qd == 0) rs += p;
            const float* vrow = Vs + j*ATTN_STR;
#pragma unroll
            for (int w8 = 0; w8 < 8; w8++) {
                float4 vv = *(const float4*)(vrow + qd*4 + w8*16);
                out[w8*4+0] += p*vv.x; out[w8*4+1] += p*vv.y;
                out[w8*4+2] += p*vv.z; out[w8*4+3] += p*vv.w;
            }
        }
    }
    __syncthreads();
    if (qd == 0) rsum[qi] = rs;
    __syncthreads();
    float norm = fmaxf(fabsf(rsum[qi]), me[qi]) + 1e-6f;
    float inv = 1.f / norm;
    float* obase = g_ht + (size_t)(b*SS + t0 + qi)*DI + h*DH;
#pragma unroll
    for (int w8 = 0; w8 < 8; w8++) {
        float4 o;
        o.x = out[w8*4+0]*inv; o.y = out[w8*4+1]*inv;
        o.z = out[w8*4+2]*inv; o.w = out[w8*4+3]*inv;
        *(float4*)(obase + qd*4 + w8*16) = o;
    }
}

// ---------------- per-head LN + skip + SiLU(z) gate -> mix hi/lo ----------------
__global__ void gnmerge_kernel(const float* __restrict__ gn_g, const float* __restrict__ gn_b,
                               const float* __restrict__ skip) {
    int t = blockIdx.x, tid = threadIdx.x;
    __shared__ float red[512];
    int l = tid & 127;
    int gbase = (tid >> 7) << 7;
    float v = g_ht[(size_t)t*DI + tid];
    red[tid] = v; __syncthreads();
    for (int off = 64; off > 0; off >>= 1) { if (l < off) red[tid] += red[tid+off]; __syncthreads(); }
    float mean = red[gbase] * (1.f/128.f); __syncthreads();
    float c = v - mean;
    red[tid] = c*c; __syncthreads();
    for (int off = 64; off > 0; off >>= 1) { if (l < off) red[tid] += red[tid+off]; __syncthreads(); }
    float var = red[gbase] * (1.f/128.f);
    float y = c * rsqrtf(var + 1e-5f) * gn_g[tid] + gn_b[tid];
    y += skip[tid] * g_xc[(size_t)t*DI + tid];
    float z = g_up[(size_t)t*2*DI + DI + tid];
    y *= z / (1.f + __expf(-z));
    __nv_bfloat16 hh = __float2bfloat16(y);
    g_mix_h[(size_t)t*DI + tid] = hh;
    g_mix_l[(size_t)t*DI + tid] = __float2bfloat16(y - __bfloat162float(hh));
}

// ---------------- final LN + projection ----------------
__global__ void final_kernel(const float* __restrict__ lnf_g, const float* __restrict__ lnf_b,
                             const float* __restrict__ Wf, const float* __restrict__ bf,
                             float* __restrict__ out) {
    int b = blockIdx.x, tid = threadIdx.x;
    __shared__ float red[256];
    float v = g_h[(size_t)(b*SS + SS - 1)*D + tid];
    red[tid] = v; __syncthreads();
    for (int off = 128; off > 0; off >>= 1) { if (tid < off) red[tid] += red[tid+off]; __syncthreads(); }
    float mean = red[0] * (1.f/256.f); __syncthreads();
    float c = v - mean;
    red[tid] = c*c; __syncthreads();
    for (int off = 128; off > 0; off >>= 1) { if (tid < off) red[tid] += red[tid+off]; __syncthreads(); }
    float var = red[0] * (1.f/256.f); __syncthreads();
    float y = c * rsqrtf(var + 1e-5f) * lnf_g[tid] + lnf_b[tid];
    red[tid] = y * Wf[tid]; __syncthreads();
    for (int off = 128; off > 0; off >>= 1) { if (tid < off) red[tid] += red[tid+off]; __syncthreads(); }
    if (tid == 0) out[b] = red[0] + bf[0];
}

// ---------------- host ----------------
static float* symaddrf(const void* sym) {
    void* p = nullptr;
    cudaGetSymbolAddress(&p, sym);
    return (float*)p;
}
static __nv_bfloat16* symaddrb(const void* sym) {
    void* p = nullptr;
    cudaGetSymbolAddress(&p, sym);
    return (__nv_bfloat16*)p;
}

extern "C" void kernel_launch(void* const* d_in, const int* in_sizes, int n_in,
                              void* d_out, int out_size) {
    const float* x      = (const float*)d_in[0];
    const float* tf     = (const float*)d_in[1];
    const float* Wp     = (const float*)d_in[2];
    const float* bp     = (const float*)d_in[3];
    const float* ln_g   = (const float*)d_in[4];
    const float* ln_b   = (const float*)d_in[5];
    const float* Wup    = (const float*)d_in[6];
    const float* bup    = (const float*)d_in[7];
    const float* conv_w = (const float*)d_in[8];
    const float* conv_b = (const float*)d_in[9];
    const float* Wq     = (const float*)d_in[10];
    const float* Wk     = (const float*)d_in[11];
    const float* Wv     = (const float*)d_in[12];
    const float* Wif    = (const float*)d_in[13];
    const float* bif    = (const float*)d_in[14];
    const float* gn_g   = (const float*)d_in[15];
    const float* gn_b   = (const float*)d_in[16];
    const float* skip   = (const float*)d_in[17];
    const float* Wdown  = (const float*)d_in[18];
    const float* bdown  = (const float*)d_in[19];
    const float* lnf_g  = (const float*)d_in[20];
    const float* lnf_b  = (const float*)d_in[21];
    const float* Wf     = (const float*)d_in[22];
    const float* bf     = (const float*)d_in[23];
    float* out = (float*)d_out;

    float* p_h   = symaddrf(g_h);
    float* p_up  = symaddrf(g_up);
    __nv_bfloat16* p_hn_h = symaddrb(g_hn_h);
    __nv_bfloat16* p_hn_l = symaddrb(g_hn_l);
    __nv_bfloat16* p_xc_h = symaddrb(g_xc_h);
    __nv_bfloat16* p_xc_l = symaddrb(g_xc_l);
    __nv_bfloat16* p_xm_h = symaddrb(g_xm_h);
    __nv_bfloat16* p_xm_l = symaddrb(g_xm_l);
    __nv_bfloat16* p_mix_h = symaddrb(g_mix_h);
    __nv_bfloat16* p_mix_l = symaddrb(g_mix_l);
    __nv_bfloat16* p_wt_h = symaddrb(g_wt_h);
    __nv_bfloat16* p_wt_l = symaddrb(g_wt_l);
    float* p_q = symaddrf(g_q);
    float* p_k = symaddrf(g_k);
    float* p_v = symaddrf(g_v);

    cudaFuncSetAttribute(attn_kernel, cudaFuncAttributeMaxDynamicSharedMemorySize, ATTN_SMEM);

    // weight prep (all layers)
    dim3 wblk(32, 8);
    for (int l = 0; l < NL; l++) {
        size_t wo = (size_t)l * WT_L;
        wsplit_kernel<<<dim3(D/32, 2*DI/32), wblk>>>(Wup + (size_t)l*D*2*DI, D, 2*DI,
                                                     p_wt_h + wo + WT_UP_OFF, p_wt_l + wo + WT_UP_OFF);
        wsplit_kernel<<<dim3(DI/32, DI/32), wblk>>>(Wq + (size_t)l*DI*DI, DI, DI,
                                                    p_wt_h + wo + WT_Q_OFF, p_wt_l + wo + WT_Q_OFF);
        wsplit_kernel<<<dim3(DI/32, DI/32), wblk>>>(Wk + (size_t)l*DI*DI, DI, DI,
                                                    p_wt_h + wo + WT_K_OFF, p_wt_l + wo + WT_K_OFF);
        wsplit_kernel<<<dim3(DI/32, DI/32), wblk>>>(Wv + (size_t)l*DI*DI, DI, DI,
                                                    p_wt_h + wo + WT_V_OFF, p_wt_l + wo + WT_V_OFF);
        wsplit_kernel<<<dim3(DI/32, D/32), wblk>>>(Wdown + (size_t)l*DI*D, DI, D,
                                                   p_wt_h + wo + WT_DN_OFF, p_wt_l + wo + WT_DN_OFF);
    }

    embed_kernel<<<NT, 256>>>(x, tf, Wp, bp);

    for (int l = 0; l < NL; l++) {
        size_t wo = (size_t)l * WT_L;
        ln256_kernel<<<NT, 256>>>(p_h, ln_g + l*D, ln_b + l*D);

        // up: (8192x256)@(256x1024)+bup -> g_up fp32
        mmagemm_kernel<<<dim3(NT/128, 1024/128), 256>>>(
            p_hn_h, p_hn_l, D, p_wt_h + wo + WT_UP_OFF, p_wt_l + wo + WT_UP_OFF,
            bup + l*2*DI, nullptr, p_up, 2*DI, D);

        conv_kernel<<<NT*DI/256, 256>>>(conv_w + l*KC*DI, conv_b + l*DI);
        split_kernel<<<NT*DI/256, 256>>>(p_up, 2*DI, DI, p_xm_h, p_xm_l);

        mmagemm_kernel<<<dim3(NT/128, DI/128), 256>>>(
            p_xc_h, p_xc_l, DI, p_wt_h + wo + WT_Q_OFF, p_wt_l + wo + WT_Q_OFF,
            nullptr, nullptr, p_q, DI, DI);
        mmagemm_kernel<<<dim3(NT/128, DI/128), 256>>>(
            p_xc_h, p_xc_l, DI, p_wt_h + wo + WT_K_OFF, p_wt_l + wo + WT_K_OFF,
            nullptr, nullptr, p_k, DI, DI);
        mmagemm_kernel<<<dim3(NT/128, DI/128), 256>>>(
            p_xm_h, p_xm_l, DI, p_wt_h + wo + WT_V_OFF, p_wt_l + wo + WT_V_OFF,
            nullptr, nullptr, p_v, DI, DI);

        gates_kernel<<<NT, 256>>>(Wif + (size_t)l*3*DI*2*NH, bif + l*2*NH);
        gatescan_kernel<<<1, 32>>>();

        attn_kernel<<<dim3(SS/64, NBH), 256, ATTN_SMEM>>>();

        gnmerge_kernel<<<NT, 512>>>(gn_g + l*DI, gn_b + l*DI, skip + l*DI);

        // down: (8192x512)@(512x256)+bdown+residual -> g_h
        mmagemm_kernel<<<dim3(NT/128, D/128), 256>>>(
            p_mix_h, p_mix_l, DI, p_wt_h + wo + WT_DN_OFF, p_wt_l + wo + WT_DN_OFF,
            bdown + l*D, p_h, p_h, D, DI);
    }

    final_kernel<<<NB, 256>>>(lnf_g, lnf_b, Wf, bf, out);
}

// round 4
// speedup vs baseline: 3.9702x; 3.5015x over previous
#include <cuda_runtime.h>
#include <cuda_bf16.h>
#include <math.h>
#include <stdint.h>

#define D   256
#define DI  512
#define NH  4
#define DH  128
#define NL  4
#define KC  4
#define NB  8
#define SS  1024
#define NT  (NB*SS)   /* 8192 tokens */
#define NBH (NB*NH)   /* 32 */

// ---------------- scratch (device globals; no allocation) ----------------
__device__ float g_h [NT*D];
__device__ float g_up[NT*2*DI];
__device__ float g_xc[NT*DI];
__device__ float g_q [NT*DI];
__device__ float g_k [NT*DI];
__device__ float g_v [NT*DI];
__device__ float g_ht[NT*DI];
__device__ float g_gates[NT*2*NH];
__device__ float g_alpha[NBH*SS];
__device__ float g_beta [NBH*SS];
__device__ float g_m    [NBH*SS];

// bf16 hi/lo split activations
__device__ __nv_bfloat16 g_hn_h[NT*D],  g_hn_l[NT*D];
__device__ __nv_bfloat16 g_xc_h[NT*DI], g_xc_l[NT*DI];
__device__ __nv_bfloat16 g_xm_h[NT*DI], g_xm_l[NT*DI];
__device__ __nv_bfloat16 g_mix_h[NT*DI], g_mix_l[NT*DI];

// bf16 hi/lo transposed weights [N,K] per layer
#define WT_UP_OFF   0
#define WT_Q_OFF    262144
#define WT_K_OFF    524288
#define WT_V_OFF    786432
#define WT_DN_OFF   1048576
#define WT_L        1179648
__device__ __nv_bfloat16 g_wt_h[NL*WT_L], g_wt_l[NL*WT_L];

__device__ __forceinline__ uint32_t smem_u32(const void* p) {
    uint32_t a;
    asm("{ .reg .u64 t; cvta.to.shared.u64 t, %1; cvt.u32.u64 %0, t; }" : "=r"(a) : "l"(p));
    return a;
}
__device__ __forceinline__ void ldmx4(uint32_t* r, uint32_t addr) {
    asm volatile("ldmatrix.sync.aligned.m8n8.x4.shared.b16 {%0,%1,%2,%3}, [%4];"
        : "=r"(r[0]), "=r"(r[1]), "=r"(r[2]), "=r"(r[3]) : "r"(addr));
}
__device__ __forceinline__ void mma16816(float* d, const uint32_t* a, const uint32_t* b) {
    asm volatile(
        "mma.sync.aligned.m16n8k16.row.col.f32.bf16.bf16.f32 "
        "{%0,%1,%2,%3}, {%4,%5,%6,%7}, {%8,%9}, {%0,%1,%2,%3};"
        : "+f"(d[0]), "+f"(d[1]), "+f"(d[2]), "+f"(d[3])
        : "r"(a[0]), "r"(a[1]), "r"(a[2]), "r"(a[3]), "r"(b[0]), "r"(b[1]));
}
__device__ __forceinline__ uint32_t packbf2(float lo, float hi) {
    __nv_bfloat162 p = __floats2bfloat162_rn(lo, hi);
    return *(uint32_t*)&p;
}

// ---------------- embed ----------------
__global__ void embed_kernel(const float* __restrict__ x, const float* __restrict__ tf,
                             const float* __restrict__ Wp, const float* __restrict__ bp) {
    int t = blockIdx.x, d = threadIdx.x;
    float acc = bp[d] + x[t] * Wp[d];
#pragma unroll
    for (int j = 0; j < 4; j++) acc += tf[t*4 + j] * Wp[(1+j)*D + d];
    g_h[t*D + d] = acc;
}

// ---------------- LayerNorm over D=256 -> bf16 hi/lo ----------------
__global__ void ln256_kernel(const float* __restrict__ in, const float* __restrict__ g,
                             const float* __restrict__ b) {
    int t = blockIdx.x, tid = threadIdx.x;
    __shared__ float red[256];
    float v = in[t*256 + tid];
    red[tid] = v; __syncthreads();
    for (int off = 128; off > 0; off >>= 1) { if (tid < off) red[tid] += red[tid+off]; __syncthreads(); }
    float mean = red[0] * (1.f/256.f); __syncthreads();
    float c = v - mean;
    red[tid] = c*c; __syncthreads();
    for (int off = 128; off > 0; off >>= 1) { if (tid < off) red[tid] += red[tid+off]; __syncthreads(); }
    float var = red[0] * (1.f/256.f);
    float y = c * rsqrtf(var + 1e-5f) * g[tid] + b[tid];
    __nv_bfloat16 h = __float2bfloat16(y);
    g_hn_h[t*256 + tid] = h;
    g_hn_l[t*256 + tid] = __float2bfloat16(y - __bfloat162float(h));
}

// ---------------- weight transpose + split ----------------
__global__ void wsplit_kernel(const float* __restrict__ W, int K, int N,
                              __nv_bfloat16* __restrict__ th, __nv_bfloat16* __restrict__ tl) {
    __shared__ float tile[32][33];
    int k0 = blockIdx.x*32, n0 = blockIdx.y*32;
    int tx = threadIdx.x, ty = threadIdx.y;
    for (int i = ty; i < 32; i += 8)
        tile[i][tx] = W[(size_t)(k0+i)*N + n0 + tx];
    __syncthreads();
    for (int i = ty; i < 32; i += 8) {
        float v = tile[tx][i];
        __nv_bfloat16 h = __float2bfloat16(v);
        size_t o = (size_t)(n0+i)*K + k0 + tx;
        th[o] = h;
        tl[o] = __float2bfloat16(v - __bfloat162float(h));
    }
}

// ---------------- activation split ----------------
__global__ void split_kernel(const float* __restrict__ src, int srcld, int cols,
                             __nv_bfloat16* __restrict__ hi, __nv_bfloat16* __restrict__ lo) {
    int idx = blockIdx.x * blockDim.x + threadIdx.x;
    int t = idx / cols, c = idx - t*cols;
    float v = src[(size_t)t*srcld + c];
    __nv_bfloat16 h = __float2bfloat16(v);
    hi[idx] = h;
    lo[idx] = __float2bfloat16(v - __bfloat162float(h));
}

// ================= mma.sync split-bf16 GEMM (unchanged, validated) =================
#define TSTR 40

__global__ void __launch_bounds__(256, 1)
mmagemm_kernel(const __nv_bfloat16* __restrict__ Ah, const __nv_bfloat16* __restrict__ Al, int lda,
               const __nv_bfloat16* __restrict__ Bh, const __nv_bfloat16* __restrict__ Bl,
               const float* __restrict__ bias, const float* __restrict__ resid,
               float* __restrict__ C, int ldc, int K) {
    __shared__ __align__(16) __nv_bfloat16 sAh[128*TSTR];
    __shared__ __align__(16) __nv_bfloat16 sAl[128*TSTR];
    __shared__ __align__(16) __nv_bfloat16 sBh[128*TSTR];
    __shared__ __align__(16) __nv_bfloat16 sBl[128*TSTR];

    int tid = threadIdx.x;
    int warp = tid >> 5, lane = tid & 31;
    int wm = warp >> 1, wn = warp & 1;
    int rowBase = blockIdx.x * 128;
    int colBase = blockIdx.y * 128;

    const __nv_bfloat16* Ah0 = Ah + (size_t)rowBase*lda;
    const __nv_bfloat16* Al0 = Al + (size_t)rowBase*lda;
    const __nv_bfloat16* Bh0 = Bh + (size_t)colBase*K;
    const __nv_bfloat16* Bl0 = Bl + (size_t)colBase*K;

    float acc[2][8][4];
#pragma unroll
    for (int mt = 0; mt < 2; mt++)
#pragma unroll
        for (int nt = 0; nt < 8; nt++)
#pragma unroll
            for (int i = 0; i < 4; i++) acc[mt][nt][i] = 0.f;

    uint32_t aoff[2][2], boff[4][2];
#pragma unroll
    for (int mt = 0; mt < 2; mt++)
#pragma unroll
        for (int ks = 0; ks < 2; ks++)
            aoff[mt][ks] = ((wm*32 + mt*16 + (lane & 15))*TSTR + ks*16 + ((lane >> 4) << 3))*2;
#pragma unroll
    for (int ntp = 0; ntp < 4; ntp++)
#pragma unroll
        for (int ks = 0; ks < 2; ks++)
            boff[ntp][ks] = ((wn*64 + ntp*16 + ((lane >> 4) << 3) + (lane & 7))*TSTR
                             + ks*16 + (((lane >> 3) & 1) << 3))*2;

    uint32_t sAh_b = smem_u32(sAh), sAl_b = smem_u32(sAl);
    uint32_t sBh_b = smem_u32(sBh), sBl_b = smem_u32(sBl);

    int nch = K >> 5;
    for (int ch = 0; ch < nch; ch++) {
        int k0 = ch << 5;
        __syncthreads();
#pragma unroll
        for (int j = 0; j < 2; j++) {
            int i = tid + j*256;
            int row = i >> 2, quad = i & 3;
            size_t go = (size_t)row*lda + k0 + quad*8;
            uint32_t so = (row*TSTR + quad*8)*2;
            *(uint4*)((char*)sAh + so) = *(const uint4*)(Ah0 + go);
            *(uint4*)((char*)sAl + so) = *(const uint4*)(Al0 + go);
            size_t gb = (size_t)row*K + k0 + quad*8;
            *(uint4*)((char*)sBh + so) = *(const uint4*)(Bh0 + gb);
            *(uint4*)((char*)sBl + so) = *(const uint4*)(Bl0 + gb);
        }
        __syncthreads();

#pragma unroll
        for (int ks = 0; ks < 2; ks++) {
            uint32_t ah[2][4], al[2][4], bh[4][4], bl[4][4];
#pragma unroll
            for (int mt = 0; mt < 2; mt++) {
                ldmx4(ah[mt], sAh_b + aoff[mt][ks]);
                ldmx4(al[mt], sAl_b + aoff[mt][ks]);
            }
#pragma unroll
            for (int ntp = 0; ntp < 4; ntp++) {
                ldmx4(bh[ntp], sBh_b + boff[ntp][ks]);
                ldmx4(bl[ntp], sBl_b + boff[ntp][ks]);
            }
#pragma unroll
            for (int mt = 0; mt < 2; mt++)
#pragma unroll
                for (int nt = 0; nt < 8; nt++) {
                    int p = nt >> 1, hh = (nt & 1) * 2;
                    mma16816(acc[mt][nt], ah[mt], &bh[p][hh]);
                    mma16816(acc[mt][nt], al[mt], &bh[p][hh]);
                    mma16816(acc[mt][nt], ah[mt], &bl[p][hh]);
                }
        }
    }

    int r0b = rowBase + wm*32 + (lane >> 2);
    int cb  = colBase + wn*64 + (lane & 3)*2;
#pragma unroll
    for (int mt = 0; mt < 2; mt++) {
#pragma unroll
        for (int nt = 0; nt < 8; nt++) {
            int col = cb + nt*8;
#pragma unroll
            for (int half = 0; half < 2; half++) {
                int row = r0b + mt*16 + half*8;
                float vx = acc[mt][nt][half*2+0];
                float vy = acc[mt][nt][half*2+1];
                if (bias) { vx += bias[col]; vy += bias[col+1]; }
                if (resid) {
                    const float2 r2 = *(const float2*)(resid + (size_t)row*ldc + col);
                    vx += r2.x; vy += r2.y;
                }
                float2 o; o.x = vx; o.y = vy;
                *(float2*)(C + (size_t)row*ldc + col) = o;
            }
        }
    }
}

// ---------------- causal depthwise conv (K=4) + SiLU ----------------
__global__ void conv_kernel(const float* __restrict__ w, const float* __restrict__ bias) {
    int idx = blockIdx.x * blockDim.x + threadIdx.x;
    int c = idx % DI;
    int t = idx / DI;
    int s = t % SS;
    float acc = bias[c];
#pragma unroll
    for (int j = 0; j < KC; j++) {
        int ss = s - 3 + j;
        if (ss >= 0) acc += g_up[(size_t)(t - 3 + j)*2*DI + c] * w[j*DI + c];
    }
    float y = acc / (1.f + __expf(-acc));
    g_xc[idx] = y;
    __nv_bfloat16 h = __float2bfloat16(y);
    g_xc_h[idx] = h;
    g_xc_l[idx] = __float2bfloat16(y - __bfloat162float(h));
}

// ---------------- gate projection ----------------
__global__ void gates_kernel(const float* __restrict__ Wif, const float* __restrict__ bif) {
    int t = blockIdx.x, tid = threadIdx.x;
    __shared__ float red[256*8];
    float p[8];
#pragma unroll
    for (int g8 = 0; g8 < 8; g8++) p[g8] = 0.f;
    for (int i = tid; i < 3*DI; i += 256) {
        float val = (i < DI) ? g_q[(size_t)t*DI + i]
                  : (i < 2*DI) ? g_k[(size_t)t*DI + i - DI]
                               : g_v[(size_t)t*DI + i - 2*DI];
        const float* wr = Wif + i*8;
#pragma unroll
        for (int g8 = 0; g8 < 8; g8++) p[g8] += val * wr[g8];
    }
#pragma unroll
    for (int g8 = 0; g8 < 8; g8++) red[tid*8 + g8] = p[g8];
    __syncthreads();
    for (int off = 128; off > 0; off >>= 1) {
        if (tid < off) {
#pragma unroll
            for (int g8 = 0; g8 < 8; g8++) red[tid*8 + g8] += red[(tid+off)*8 + g8];
        }
        __syncthreads();
    }
    if (tid < 8) g_gates[t*8 + tid] = red[tid] + bif[tid];
}

// ---------------- gate scan: warp-parallel segmented scans ----------------
__global__ void gatescan_kernel() {
    int bh = blockIdx.x;
    int lane = threadIdx.x;
    int b = bh >> 2, h = bh & 3;
    float carryF = 0.f, carryM = -1e30f;
    for (int c = 0; c < SS/32; c++) {
        int t = c*32 + lane;
        const float* gp = g_gates + (size_t)(b*SS + t)*8;
        float fp = gp[NH + h], ipv = gp[h];
        float lf = (fp >= 0.f) ? -log1pf(__expf(-fp)) : fp - log1pf(__expf(fp));
        // inclusive scan (add)
        float s = lf;
#pragma unroll
        for (int d = 1; d < 32; d <<= 1) {
            float v = __shfl_up_sync(0xFFFFFFFFu, s, d);
            if (lane >= d) s += v;
        }
        float Fc = carryF + s;
        float bt = ipv - Fc;
        // inclusive scan (max)
        float mx = bt;
#pragma unroll
        for (int d = 1; d < 32; d <<= 1) {
            float v = __shfl_up_sync(0xFFFFFFFFu, mx, d);
            if (lane >= d) mx = fmaxf(mx, v);
        }
        float rmax = fmaxf(carryM, mx);
        g_beta [bh*SS + t] = bt;
        g_alpha[bh*SS + t] = -rmax;
        g_m    [bh*SS + t] = Fc + rmax;
        carryF += __shfl_sync(0xFFFFFFFFu, s, 31);
        carryM  = fmaxf(carryM, __shfl_sync(0xFFFFFFFFu, rmax, 31));
    }
}

// ================= mma.sync mLSTM attention =================
// block: (qt of 128 q-rows, bh). 8 warps, warp w -> 16 q-rows.
// s-tiles of 32. Q/K in smem [rows][d] bf16 hi/lo, V transposed [d][s].
#define STRQ 136   /* bf16 elems; 272B rows, 16B-mult, conflict-free ldmatrix */
#define STRV 40    /* 80B rows */
#define A2_QH 0
#define A2_QL (A2_QH + 128*STRQ*2)
#define A2_KH (A2_QL + 128*STRQ*2)
#define A2_KL (A2_KH + 32*STRQ*2)
#define A2_VH (A2_KL + 32*STRQ*2)
#define A2_VL (A2_VH + 128*STRV*2)
#define A2_BT (A2_VL + 128*STRV*2)
#define ATTN2_SMEM (A2_BT + 32*4)
#define SCALE 0.08838834764831845f

__global__ void __launch_bounds__(256, 1) attn2_kernel() {
    extern __shared__ char sm2[];
    __nv_bfloat16* Qh = (__nv_bfloat16*)(sm2 + A2_QH);
    __nv_bfloat16* Ql = (__nv_bfloat16*)(sm2 + A2_QL);
    __nv_bfloat16* Kh = (__nv_bfloat16*)(sm2 + A2_KH);
    __nv_bfloat16* Kl = (__nv_bfloat16*)(sm2 + A2_KL);
    __nv_bfloat16* Vh = (__nv_bfloat16*)(sm2 + A2_VH);
    __nv_bfloat16* Vl = (__nv_bfloat16*)(sm2 + A2_VL);
    float* bts = (float*)(sm2 + A2_BT);

    int qt = blockIdx.x, bh = blockIdx.y;
    int b = bh >> 2, h = bh & 3;
    int tid = threadIdx.x, warp = tid >> 5, lane = tid & 31;
    int t0 = qt * 128;

    // load Q tile (128 x 128) fp32 -> bf16 hi/lo
#pragma unroll
    for (int j = 0; j < 16; j++) {
        int i = tid + j*256;                 // 0..4095 float4 units
        int row = i >> 5, c4 = (i & 31)*4;
        float4 v = *(const float4*)(g_q + (size_t)(b*SS + t0 + row)*DI + h*DH + c4);
        __nv_bfloat16 h0 = __float2bfloat16(v.x), h1 = __float2bfloat16(v.y);
        __nv_bfloat16 h2 = __float2bfloat16(v.z), h3 = __float2bfloat16(v.w);
        __nv_bfloat16* qh = Qh + row*STRQ + c4;
        __nv_bfloat16* ql = Ql + row*STRQ + c4;
        qh[0]=h0; qh[1]=h1; qh[2]=h2; qh[3]=h3;
        ql[0]=__float2bfloat16(v.x-__bfloat162float(h0));
        ql[1]=__float2bfloat16(v.y-__bfloat162float(h1));
        ql[2]=__float2bfloat16(v.z-__bfloat162float(h2));
        ql[3]=__float2bfloat16(v.w-__bfloat162float(h3));
    }

    // per-thread fixed rows
    int tr0 = t0 + warp*16 + (lane >> 2);
    int tr1 = tr0 + 8;
    float al0 = g_alpha[bh*SS + tr0];
    float al1 = g_alpha[bh*SS + tr1];

    float O[16][4];
#pragma unroll
    for (int nt = 0; nt < 16; nt++)
#pragma unroll
        for (int i = 0; i < 4; i++) O[nt][i] = 0.f;
    float rs0 = 0.f, rs1 = 0.f;

    uint32_t sQh = smem_u32(Qh), sQl = smem_u32(Ql);
    uint32_t sKh = smem_u32(Kh), sKl = smem_u32(Kl);
    uint32_t sVh = smem_u32(Vh), sVl = smem_u32(Vl);

    // ldmatrix offsets
    uint32_t qoff[8], koff[2][8], voff[8][2];
#pragma unroll
    for (int ks = 0; ks < 8; ks++)
        qoff[ks] = ((warp*16 + (lane & 15))*STRQ + ks*16 + ((lane >> 4) << 3))*2;
#pragma unroll
    for (int np = 0; np < 2; np++)
#pragma unroll
        for (int ks = 0; ks < 8; ks++)
            koff[np][ks] = ((np*16 + ((lane >> 4) << 3) + (lane & 7))*STRQ
                            + ks*16 + (((lane >> 3) & 1) << 3))*2;
#pragma unroll
    for (int np = 0; np < 8; np++)
#pragma unroll
        for (int kv = 0; kv < 2; kv++)
            voff[np][kv] = ((np*16 + ((lane >> 4) << 3) + (lane & 7))*STRV
                            + kv*16 + (((lane >> 3) & 1) << 3))*2;

    int nst = 4*(qt + 1);
    for (int st = 0; st < nst; st++) {
        int s0 = st * 32;
        __syncthreads();
        // load K tile (32 x 128) and V tile (transposed) + bt
#pragma unroll
        for (int j = 0; j < 4; j++) {
            int i = tid + j*256;             // 0..1023 float4 units
            int row = i >> 5, c4 = (i & 31)*4;
            size_t gbase = (size_t)(b*SS + s0 + row)*DI + h*DH + c4;
            float4 kv4 = *(const float4*)(g_k + gbase);
            __nv_bfloat16 h0 = __float2bfloat16(kv4.x), h1 = __float2bfloat16(kv4.y);
            __nv_bfloat16 h2 = __float2bfloat16(kv4.z), h3 = __float2bfloat16(kv4.w);
            __nv_bfloat16* kh = Kh + row*STRQ + c4;
            __nv_bfloat16* kl = Kl + row*STRQ + c4;
            kh[0]=h0; kh[1]=h1; kh[2]=h2; kh[3]=h3;
            kl[0]=__float2bfloat16(kv4.x-__bfloat162float(h0));
            kl[1]=__float2bfloat16(kv4.y-__bfloat162float(h1));
            kl[2]=__float2bfloat16(kv4.z-__bfloat162float(h2));
            kl[3]=__float2bfloat16(kv4.w-__bfloat162float(h3));
            float4 vv4 = *(const float4*)(g_v + gbase);
            float vf[4] = {vv4.x, vv4.y, vv4.z, vv4.w};
#pragma unroll
            for (int e = 0; e < 4; e++) {
                __nv_bfloat16 vh = __float2bfloat16(vf[e]);
                Vh[(c4+e)*STRV + row] = vh;
                Vl[(c4+e)*STRV + row] = __float2bfloat16(vf[e]-__bfloat162float(vh));
            }
        }
        if (tid < 32) bts[tid] = g_beta[bh*SS + s0 + tid];
        __syncthreads();

        // ---- S = Q K^T (3-pass split) ----
        float S[4][4];
#pragma unroll
        for (int nt = 0; nt < 4; nt++)
#pragma unroll
            for (int i = 0; i < 4; i++) S[nt][i] = 0.f;
#pragma unroll
        for (int ks = 0; ks < 8; ks++) {
            uint32_t ah[4], al[4], bkh[2][4], bkl[2][4];
            ldmx4(ah, sQh + qoff[ks]);
            ldmx4(al, sQl + qoff[ks]);
            ldmx4(bkh[0], sKh + koff[0][ks]);
            ldmx4(bkh[1], sKh + koff[1][ks]);
            ldmx4(bkl[0], sKl + koff[0][ks]);
            ldmx4(bkl[1], sKl + koff[1][ks]);
#pragma unroll
            for (int nt = 0; nt < 4; nt++) {
                int p = nt >> 1, hh = (nt & 1)*2;
                mma16816(S[nt], ah, &bkh[p][hh]);
                mma16816(S[nt], al, &bkh[p][hh]);
                mma16816(S[nt], ah, &bkl[p][hh]);
            }
        }

        // ---- elementwise: mask, gate-weight, scale; pack P to bf16 hi/lo ----
        uint32_t Ph[2][4], Pl[2][4];
#pragma unroll
        for (int nt = 0; nt < 4; nt++) {
            float pv[4], plv[4];
#pragma unroll
            for (int r = 0; r < 4; r++) {
                int trow = (r < 2) ? tr0 : tr1;
                float alv = (r < 2) ? al0 : al1;
                int cl = nt*8 + (lane & 3)*2 + (r & 1);
                int sc = s0 + cl;
                float w = (sc <= trow) ? __expf(alv + bts[cl]) : 0.f;
                float p = S[nt][r] * SCALE * w;
                if (r < 2) rs0 += p; else rs1 += p;
                pv[r] = p;
                float ph = __bfloat162float(__float2bfloat16(p));
                plv[r] = p - ph;
            }
            int kv = nt >> 1;
            if ((nt & 1) == 0) {
                Ph[kv][0] = packbf2(pv[0], pv[1]);
                Ph[kv][1] = packbf2(pv[2], pv[3]);
                Pl[kv][0] = packbf2(plv[0], plv[1]);
                Pl[kv][1] = packbf2(plv[2], plv[3]);
            } else {
                Ph[kv][2] = packbf2(pv[0], pv[1]);
                Ph[kv][3] = packbf2(pv[2], pv[3]);
                Pl[kv][2] = packbf2(plv[0], plv[1]);
                Pl[kv][3] = packbf2(plv[2], plv[3]);
            }
        }

        // ---- O += P V (3-pass split) ----
#pragma unroll
        for (int kv = 0; kv < 2; kv++) {
#pragma unroll
            for (int np = 0; np < 8; np++) {
                uint32_t bvh[4], bvl[4];
                ldmx4(bvh, sVh + voff[np][kv]);
                ldmx4(bvl, sVl + voff[np][kv]);
#pragma unroll
                for (int hh = 0; hh < 2; hh++) {
                    int nt = np*2 + hh;
                    mma16816(O[nt], Ph[kv], &bvh[hh*2]);
                    mma16816(O[nt], Pl[kv], &bvh[hh*2]);
                    mma16816(O[nt], Ph[kv], &bvl[hh*2]);
                }
            }
        }
    }

    // ---- normalizer: reduce row sums across the 4 lanes of each row ----
    rs0 += __shfl_xor_sync(0xFFFFFFFFu, rs0, 1);
    rs0 += __shfl_xor_sync(0xFFFFFFFFu, rs0, 2);
    rs1 += __shfl_xor_sync(0xFFFFFFFFu, rs1, 1);
    rs1 += __shfl_xor_sync(0xFFFFFFFFu, rs1, 2);
    float me0 = __expf(-g_m[bh*SS + tr0]);
    float me1 = __expf(-g_m[bh*SS + tr1]);
    float inv0 = 1.f / (fmaxf(fabsf(rs0), me0) + 1e-6f);
    float inv1 = 1.f / (fmaxf(fabsf(rs1), me1) + 1e-6f);

    float* o0 = g_ht + (size_t)(b*SS + tr0)*DI + h*DH + (lane & 3)*2;
    float* o1 = g_ht + (size_t)(b*SS + tr1)*DI + h*DH + (lane & 3)*2;
#pragma unroll
    for (int nt = 0; nt < 16; nt++) {
        float2 v0; v0.x = O[nt][0]*inv0; v0.y = O[nt][1]*inv0;
        float2 v1; v1.x = O[nt][2]*inv1; v1.y = O[nt][3]*inv1;
        *(float2*)(o0 + nt*8) = v0;
        *(float2*)(o1 + nt*8) = v1;
    }
}

// ---------------- per-head LN + skip + SiLU(z) gate -> mix hi/lo ----------------
__global__ void gnmerge_kernel(const float* __restrict__ gn_g, const float* __restrict__ gn_b,
                               const float* __restrict__ skip) {
    int t = blockIdx.x, tid = threadIdx.x;
    __shared__ float red[512];
    int l = tid & 127;
    int gbase = (tid >> 7) << 7;
    float v = g_ht[(size_t)t*DI + tid];
    red[tid] = v; __syncthreads();
    for (int off = 64; off > 0; off >>= 1) { if (l < off) red[tid] += red[tid+off]; __syncthreads(); }
    float mean = red[gbase] * (1.f/128.f); __syncthreads();
    float c = v - mean;
    red[tid] = c*c; __syncthreads();
    for (int off = 64; off > 0; off >>= 1) { if (l < off) red[tid] += red[tid+off]; __syncthreads(); }
    float var = red[gbase] * (1.f/128.f);
    float y = c * rsqrtf(var + 1e-5f) * gn_g[tid] + gn_b[tid];
    y += skip[tid] * g_xc[(size_t)t*DI + tid];
    float z = g_up[(size_t)t*2*DI + DI + tid];
    y *= z / (1.f + __expf(-z));
    __nv_bfloat16 hh = __float2bfloat16(y);
    g_mix_h[(size_t)t*DI + tid] = hh;
    g_mix_l[(size_t)t*DI + tid] = __float2bfloat16(y - __bfloat162float(hh));
}

// ---------------- final LN + projection ----------------
__global__ void final_kernel(const float* __restrict__ lnf_g, const float* __restrict__ lnf_b,
                             const float* __restrict__ Wf, const float* __restrict__ bf,
                             float* __restrict__ out) {
    int b = blockIdx.x, tid = threadIdx.x;
    __shared__ float red[256];
    float v = g_h[(size_t)(b*SS + SS - 1)*D + tid];
    red[tid] = v; __syncthreads();
    for (int off = 128; off > 0; off >>= 1) { if (tid < off) red[tid] += red[tid+off]; __syncthreads(); }
    float mean = red[0] * (1.f/256.f); __syncthreads();
    float c = v - mean;
    red[tid] = c*c; __syncthreads();
    for (int off = 128; off > 0; off >>= 1) { if (tid < off) red[tid] += red[tid+off]; __syncthreads(); }
    float var = red[0] * (1.f/256.f); __syncthreads();
    float y = c * rsqrtf(var + 1e-5f) * lnf_g[tid] + lnf_b[tid];
    red[tid] = y * Wf[tid]; __syncthreads();
    for (int off = 128; off > 0; off >>= 1) { if (tid < off) red[tid] += red[tid+off]; __syncthreads(); }
    if (tid == 0) out[b] = red[0] + bf[0];
}

// ---------------- host ----------------
static float* symaddrf(const void* sym) {
    void* p = nullptr;
    cudaGetSymbolAddress(&p, sym);
    return (float*)p;
}
static __nv_bfloat16* symaddrb(const void* sym) {
    void* p = nullptr;
    cudaGetSymbolAddress(&p, sym);
    return (__nv_bfloat16*)p;
}

extern "C" void kernel_launch(void* const* d_in, const int* in_sizes, int n_in,
                              void* d_out, int out_size) {
    const float* x      = (const float*)d_in[0];
    const float* tf     = (const float*)d_in[1];
    const float* Wp     = (const float*)d_in[2];
    const float* bp     = (const float*)d_in[3];
    const float* ln_g   = (const float*)d_in[4];
    const float* ln_b   = (const float*)d_in[5];
    const float* Wup    = (const float*)d_in[6];
    const float* bup    = (const float*)d_in[7];
    const float* conv_w = (const float*)d_in[8];
    const float* conv_b = (const float*)d_in[9];
    const float* Wq     = (const float*)d_in[10];
    const float* Wk     = (const float*)d_in[11];
    const float* Wv     = (const float*)d_in[12];
    const float* Wif    = (const float*)d_in[13];
    const float* bif    = (const float*)d_in[14];
    const float* gn_g   = (const float*)d_in[15];
    const float* gn_b   = (const float*)d_in[16];
    const float* skip   = (const float*)d_in[17];
    const float* Wdown  = (const float*)d_in[18];
    const float* bdown  = (const float*)d_in[19];
    const float* lnf_g  = (const float*)d_in[20];
    const float* lnf_b  = (const float*)d_in[21];
    const float* Wf     = (const float*)d_in[22];
    const float* bf     = (const float*)d_in[23];
    float* out = (float*)d_out;

    float* p_h   = symaddrf(g_h);
    float* p_up  = symaddrf(g_up);
    __nv_bfloat16* p_hn_h = symaddrb(g_hn_h);
    __nv_bfloat16* p_hn_l = symaddrb(g_hn_l);
    __nv_bfloat16* p_xc_h = symaddrb(g_xc_h);
    __nv_bfloat16* p_xc_l = symaddrb(g_xc_l);
    __nv_bfloat16* p_xm_h = symaddrb(g_xm_h);
    __nv_bfloat16* p_xm_l = symaddrb(g_xm_l);
    __nv_bfloat16* p_mix_h = symaddrb(g_mix_h);
    __nv_bfloat16* p_mix_l = symaddrb(g_mix_l);
    __nv_bfloat16* p_wt_h = symaddrb(g_wt_h);
    __nv_bfloat16* p_wt_l = symaddrb(g_wt_l);
    float* p_q = symaddrf(g_q);
    float* p_k = symaddrf(g_k);
    float* p_v = symaddrf(g_v);

    cudaFuncSetAttribute(attn2_kernel, cudaFuncAttributeMaxDynamicSharedMemorySize, ATTN2_SMEM);

    // weight prep (all layers)
    dim3 wblk(32, 8);
    for (int l = 0; l < NL; l++) {
        size_t wo = (size_t)l * WT_L;
        wsplit_kernel<<<dim3(D/32, 2*DI/32), wblk>>>(Wup + (size_t)l*D*2*DI, D, 2*DI,
                                                     p_wt_h + wo + WT_UP_OFF, p_wt_l + wo + WT_UP_OFF);
        wsplit_kernel<<<dim3(DI/32, DI/32), wblk>>>(Wq + (size_t)l*DI*DI, DI, DI,
                                                    p_wt_h + wo + WT_Q_OFF, p_wt_l + wo + WT_Q_OFF);
        wsplit_kernel<<<dim3(DI/32, DI/32), wblk>>>(Wk + (size_t)l*DI*DI, DI, DI,
                                                    p_wt_h + wo + WT_K_OFF, p_wt_l + wo + WT_K_OFF);
        wsplit_kernel<<<dim3(DI/32, DI/32), wblk>>>(Wv + (size_t)l*DI*DI, DI, DI,
                                                    p_wt_h + wo + WT_V_OFF, p_wt_l + wo + WT_V_OFF);
        wsplit_kernel<<<dim3(DI/32, D/32), wblk>>>(Wdown + (size_t)l*DI*D, DI, D,
                                                   p_wt_h + wo + WT_DN_OFF, p_wt_l + wo + WT_DN_OFF);
    }

    embed_kernel<<<NT, 256>>>(x, tf, Wp, bp);

    for (int l = 0; l < NL; l++) {
        size_t wo = (size_t)l * WT_L;
        ln256_kernel<<<NT, 256>>>(p_h, ln_g + l*D, ln_b + l*D);

        mmagemm_kernel<<<dim3(NT/128, 1024/128), 256>>>(
            p_hn_h, p_hn_l, D, p_wt_h + wo + WT_UP_OFF, p_wt_l + wo + WT_UP_OFF,
            bup + l*2*DI, nullptr, p_up, 2*DI, D);

        conv_kernel<<<NT*DI/256, 256>>>(conv_w + l*KC*DI, conv_b + l*DI);
        split_kernel<<<NT*DI/256, 256>>>(p_up, 2*DI, DI, p_xm_h, p_xm_l);

        mmagemm_kernel<<<dim3(NT/128, DI/128), 256>>>(
            p_xc_h, p_xc_l, DI, p_wt_h + wo + WT_Q_OFF, p_wt_l + wo + WT_Q_OFF,
            nullptr, nullptr, p_q, DI, DI);
        mmagemm_kernel<<<dim3(NT/128, DI/128), 256>>>(
            p_xc_h, p_xc_l, DI, p_wt_h + wo + WT_K_OFF, p_wt_l + wo + WT_K_OFF,
            nullptr, nullptr, p_k, DI, DI);
        mmagemm_kernel<<<dim3(NT/128, DI/128), 256>>>(
            p_xm_h, p_xm_l, DI, p_wt_h + wo + WT_V_OFF, p_wt_l + wo + WT_V_OFF,
            nullptr, nullptr, p_v, DI, DI);

        gates_kernel<<<NT, 256>>>(Wif + (size_t)l*3*DI*2*NH, bif + l*2*NH);
        gatescan_kernel<<<NBH, 32>>>();

        attn2_kernel<<<dim3(SS/128, NBH), 256, ATTN2_SMEM>>>();

        gnmerge_kernel<<<NT, 512>>>(gn_g + l*DI, gn_b + l*DI, skip + l*DI);

        mmagemm_kernel<<<dim3(NT/128, D/128), 256>>>(
            p_mix_h, p_mix_l, DI, p_wt_h + wo + WT_DN_OFF, p_wt_l + wo + WT_DN_OFF,
            bdown + l*D, p_h, p_h, D, DI);
    }

    final_kernel<<<NB, 256>>>(lnf_g, lnf_b, Wf, bf, out);
}

// round 5
// speedup vs baseline: 4.0887x; 1.0299x over previous
#include <cuda_runtime.h>
#include <cuda_bf16.h>
#include <math.h>
#include <stdint.h>

#define D   256
#define DI  512
#define NH  4
#define DH  128
#define NL  4
#define KC  4
#define NB  8
#define SS  1024
#define NT  (NB*SS)   /* 8192 tokens */
#define NBH (NB*NH)   /* 32 */

// ---------------- scratch (device globals; no allocation) ----------------
__device__ float g_h [NT*D];
__device__ float g_up[NT*2*DI];
__device__ float g_xc[NT*DI];
__device__ float g_ht[NT*DI];
__device__ float g_gates[NT*2*NH];
__device__ float g_alpha[NBH*SS];
__device__ float g_beta [NBH*SS];
__device__ float g_m    [NBH*SS];
__device__ float g_wc   [NL*DI*16];   // combined gate weights [l][j][16]

// bf16 hi/lo split activations
__device__ __nv_bfloat16 g_hn_h[NT*D],  g_hn_l[NT*D];
__device__ __nv_bfloat16 g_xc_h[NT*DI], g_xc_l[NT*DI];
__device__ __nv_bfloat16 g_xm_h[NT*DI], g_xm_l[NT*DI];
__device__ __nv_bfloat16 g_mix_h[NT*DI], g_mix_l[NT*DI];
__device__ __nv_bfloat16 g_qh[NT*DI], g_ql[NT*DI];
__device__ __nv_bfloat16 g_kh[NT*DI], g_kl[NT*DI];
__device__ __nv_bfloat16 g_vh[NT*DI], g_vl[NT*DI];

// bf16 hi/lo transposed weights [N,K] per layer
#define WT_UP_OFF   0
#define WT_Q_OFF    262144
#define WT_K_OFF    524288
#define WT_V_OFF    786432
#define WT_DN_OFF   1048576
#define WT_L        1179648
__device__ __nv_bfloat16 g_wt_h[NL*WT_L], g_wt_l[NL*WT_L];

__device__ __forceinline__ uint32_t smem_u32(const void* p) {
    uint32_t a;
    asm("{ .reg .u64 t; cvta.to.shared.u64 t, %1; cvt.u32.u64 %0, t; }" : "=r"(a) : "l"(p));
    return a;
}
__device__ __forceinline__ void ldmx4(uint32_t* r, uint32_t addr) {
    asm volatile("ldmatrix.sync.aligned.m8n8.x4.shared.b16 {%0,%1,%2,%3}, [%4];"
        : "=r"(r[0]), "=r"(r[1]), "=r"(r[2]), "=r"(r[3]) : "r"(addr));
}
__device__ __forceinline__ void mma16816(float* d, const uint32_t* a, const uint32_t* b) {
    asm volatile(
        "mma.sync.aligned.m16n8k16.row.col.f32.bf16.bf16.f32 "
        "{%0,%1,%2,%3}, {%4,%5,%6,%7}, {%8,%9}, {%0,%1,%2,%3};"
        : "+f"(d[0]), "+f"(d[1]), "+f"(d[2]), "+f"(d[3])
        : "r"(a[0]), "r"(a[1]), "r"(a[2]), "r"(a[3]), "r"(b[0]), "r"(b[1]));
}
__device__ __forceinline__ uint32_t packbf2(float lo, float hi) {
    __nv_bfloat162 p = __floats2bfloat162_rn(lo, hi);
    return *(uint32_t*)&p;
}
__device__ __forceinline__ void cpa16(uint32_t s, const void* g) {
    asm volatile("cp.async.cg.shared.global [%0], [%1], 16;" :: "r"(s), "l"(g));
}
#define CP_COMMIT() asm volatile("cp.async.commit_group;" ::: "memory")
#define CP_WAIT0()  asm volatile("cp.async.wait_group 0;" ::: "memory")

// ---------------- embed ----------------
__global__ void embed_kernel(const float* __restrict__ x, const float* __restrict__ tf,
                             const float* __restrict__ Wp, const float* __restrict__ bp) {
    int t = blockIdx.x, d = threadIdx.x;
    float acc = bp[d] + x[t] * Wp[d];
#pragma unroll
    for (int j = 0; j < 4; j++) acc += tf[t*4 + j] * Wp[(1+j)*D + d];
    g_h[t*D + d] = acc;
}

// ---------------- LayerNorm over D=256 -> bf16 hi/lo ----------------
__global__ void ln256_kernel(const float* __restrict__ in, const float* __restrict__ g,
                             const float* __restrict__ b) {
    int t = blockIdx.x, tid = threadIdx.x;
    __shared__ float red[256];
    float v = in[t*256 + tid];
    red[tid] = v; __syncthreads();
    for (int off = 128; off > 0; off >>= 1) { if (tid < off) red[tid] += red[tid+off]; __syncthreads(); }
    float mean = red[0] * (1.f/256.f); __syncthreads();
    float c = v - mean;
    red[tid] = c*c; __syncthreads();
    for (int off = 128; off > 0; off >>= 1) { if (tid < off) red[tid] += red[tid+off]; __syncthreads(); }
    float var = red[0] * (1.f/256.f);
    float y = c * rsqrtf(var + 1e-5f) * g[tid] + b[tid];
    __nv_bfloat16 h = __float2bfloat16(y);
    g_hn_h[t*256 + tid] = h;
    g_hn_l[t*256 + tid] = __float2bfloat16(y - __bfloat162float(h));
}

// ---------------- weight transpose + split ----------------
__global__ void wsplit_kernel(const float* __restrict__ W, int K, int N,
                              __nv_bfloat16* __restrict__ th, __nv_bfloat16* __restrict__ tl) {
    __shared__ float tile[32][33];
    int k0 = blockIdx.x*32, n0 = blockIdx.y*32;
    int tx = threadIdx.x, ty = threadIdx.y;
    for (int i = ty; i < 32; i += 8)
        tile[i][tx] = W[(size_t)(k0+i)*N + n0 + tx];
    __syncthreads();
    for (int i = ty; i < 32; i += 8) {
        float v = tile[tx][i];
        __nv_bfloat16 h = __float2bfloat16(v);
        size_t o = (size_t)(n0+i)*K + k0 + tx;
        th[o] = h;
        tl[o] = __float2bfloat16(v - __bfloat162float(h));
    }
}

// ---------------- combined gate weights: W1 = Wq@Wifq + Wk@Wifk, W2 = Wv@Wifv ----------------
__global__ void wcomb_kernel(const float* __restrict__ Wq, const float* __restrict__ Wk,
                             const float* __restrict__ Wv, const float* __restrict__ Wif,
                             float* __restrict__ wc) {
    int i = blockIdx.x;
    int warp = threadIdx.x >> 5, lane = threadIdx.x & 31;   // warp = g (0..7)
    float a1 = 0.f, a2 = 0.f;
    for (int j = lane; j < DI; j += 32) {
        a1 += Wq[(size_t)i*DI + j] * Wif[j*8 + warp]
            + Wk[(size_t)i*DI + j] * Wif[(DI + j)*8 + warp];
        a2 += Wv[(size_t)i*DI + j] * Wif[(2*DI + j)*8 + warp];
    }
#pragma unroll
    for (int d = 16; d > 0; d >>= 1) {
        a1 += __shfl_xor_sync(0xFFFFFFFFu, a1, d);
        a2 += __shfl_xor_sync(0xFFFFFFFFu, a2, d);
    }
    if (lane == 0) {
        wc[i*16 + warp] = a1;
        wc[i*16 + 8 + warp] = a2;
    }
}

// ---------------- gates: gates[t] = xc[t]@W1 + xm[t]@W2 + bif ----------------
__global__ void gates2_kernel(const float* __restrict__ wc, const float* __restrict__ bif) {
    int warp = threadIdx.x >> 5, lane = threadIdx.x & 31;
    int t = blockIdx.x*8 + warp;
    float acc[8];
#pragma unroll
    for (int g = 0; g < 8; g++) acc[g] = 0.f;
    const float* xcr = g_xc + (size_t)t*DI;
    const float* xmr = g_up + (size_t)t*2*DI;
    for (int j = lane; j < DI; j += 32) {
        float xcv = xcr[j], xmv = xmr[j];
        const float* w = wc + j*16;
#pragma unroll
        for (int g = 0; g < 8; g++) acc[g] += xcv*w[g] + xmv*w[8+g];
    }
#pragma unroll
    for (int g = 0; g < 8; g++) {
#pragma unroll
        for (int d = 16; d > 0; d >>= 1) acc[g] += __shfl_xor_sync(0xFFFFFFFFu, acc[g], d);
    }
    if (lane < 8) g_gates[(size_t)t*8 + lane] = acc[lane] + bif[lane];
}

// ================= cp.async double-buffered mma.sync split-bf16 GEMM =================
#define TSTR 40
#define OFF_AH 0
#define OFF_AL 10240
#define OFF_BH 20480
#define OFF_BL 30720
#define STAGE_B 40960
#define GEMM_SMEM (2*STAGE_B)

// MODE: 0 = fp32 out (+bias,+resid)   1 = split bf16 out   2 = fp32 out + split for col<DI
template<int MODE>
__global__ void __launch_bounds__(256)
mmagemm2_kernel(const __nv_bfloat16* __restrict__ Ah, const __nv_bfloat16* __restrict__ Al, int lda,
                const __nv_bfloat16* __restrict__ Bh, const __nv_bfloat16* __restrict__ Bl,
                const float* __restrict__ bias, const float* __restrict__ resid,
                float* __restrict__ C, int ldc,
                __nv_bfloat16* __restrict__ Ohi, __nv_bfloat16* __restrict__ Olo, int ldo,
                int K) {
    extern __shared__ char dsm[];
    uint32_t sb = smem_u32(dsm);

    int tid = threadIdx.x;
    int warp = tid >> 5, lane = tid & 31;
    int wm = warp >> 1, wn = warp & 1;
    int rowBase = blockIdx.x * 128;
    int colBase = blockIdx.y * 128;

    const __nv_bfloat16* Ah0 = Ah + (size_t)rowBase*lda;
    const __nv_bfloat16* Al0 = Al + (size_t)rowBase*lda;
    const __nv_bfloat16* Bh0 = Bh + (size_t)colBase*K;
    const __nv_bfloat16* Bl0 = Bl + (size_t)colBase*K;

    float acc[2][8][4];
#pragma unroll
    for (int mt = 0; mt < 2; mt++)
#pragma unroll
        for (int nt = 0; nt < 8; nt++)
#pragma unroll
            for (int i = 0; i < 4; i++) acc[mt][nt][i] = 0.f;

    uint32_t aoff[2][2], boff[4][2];
#pragma unroll
    for (int mt = 0; mt < 2; mt++)
#pragma unroll
        for (int ks = 0; ks < 2; ks++)
            aoff[mt][ks] = ((wm*32 + mt*16 + (lane & 15))*TSTR + ks*16 + ((lane >> 4) << 3))*2;
#pragma unroll
    for (int ntp = 0; ntp < 4; ntp++)
#pragma unroll
        for (int ks = 0; ks < 2; ks++)
            boff[ntp][ks] = ((wn*64 + ntp*16 + ((lane >> 4) << 3) + (lane & 7))*TSTR
                             + ks*16 + (((lane >> 3) & 1) << 3))*2;

    int ldRow = tid >> 2, ldQuad = tid & 3;     // rows tid/4, tid/4+64
    uint32_t soA = (ldRow*TSTR + ldQuad*8)*2;
    uint32_t soB = ((ldRow+64)*TSTR + ldQuad*8)*2;

    int nch = K >> 5;
    // prefetch chunk 0 into stage 0
    {
        uint32_t st = sb;
        cpa16(st + OFF_AH + soA, Ah0 + (size_t)ldRow*lda + ldQuad*8);
        cpa16(st + OFF_AL + soA, Al0 + (size_t)ldRow*lda + ldQuad*8);
        cpa16(st + OFF_BH + soA, Bh0 + (size_t)ldRow*K + ldQuad*8);
        cpa16(st + OFF_BL + soA, Bl0 + (size_t)ldRow*K + ldQuad*8);
        cpa16(st + OFF_AH + soB, Ah0 + (size_t)(ldRow+64)*lda + ldQuad*8);
        cpa16(st + OFF_AL + soB, Al0 + (size_t)(ldRow+64)*lda + ldQuad*8);
        cpa16(st + OFF_BH + soB, Bh0 + (size_t)(ldRow+64)*K + ldQuad*8);
        cpa16(st + OFF_BL + soB, Bl0 + (size_t)(ldRow+64)*K + ldQuad*8);
        CP_COMMIT();
    }

    int buf = 0;
    for (int ch = 0; ch < nch; ch++) {
        CP_WAIT0();
        __syncthreads();
        if (ch + 1 < nch) {
            int k1 = (ch + 1) << 5;
            uint32_t st = sb + (buf ^ 1)*STAGE_B;
            cpa16(st + OFF_AH + soA, Ah0 + (size_t)ldRow*lda + k1 + ldQuad*8);
            cpa16(st + OFF_AL + soA, Al0 + (size_t)ldRow*lda + k1 + ldQuad*8);
            cpa16(st + OFF_BH + soA, Bh0 + (size_t)ldRow*K + k1 + ldQuad*8);
            cpa16(st + OFF_BL + soA, Bl0 + (size_t)ldRow*K + k1 + ldQuad*8);
            cpa16(st + OFF_AH + soB, Ah0 + (size_t)(ldRow+64)*lda + k1 + ldQuad*8);
            cpa16(st + OFF_AL + soB, Al0 + (size_t)(ldRow+64)*lda + k1 + ldQuad*8);
            cpa16(st + OFF_BH + soB, Bh0 + (size_t)(ldRow+64)*K + k1 + ldQuad*8);
            cpa16(st + OFF_BL + soB, Bl0 + (size_t)(ldRow+64)*K + k1 + ldQuad*8);
            CP_COMMIT();
        }
        uint32_t st = sb + buf*STAGE_B;
        uint32_t sAh_b = st + OFF_AH, sAl_b = st + OFF_AL;
        uint32_t sBh_b = st + OFF_BH, sBl_b = st + OFF_BL;
#pragma unroll
        for (int ks = 0; ks < 2; ks++) {
            uint32_t ah[2][4], al[2][4], bh[4][4], bl[4][4];
#pragma unroll
            for (int mt = 0; mt < 2; mt++) {
                ldmx4(ah[mt], sAh_b + aoff[mt][ks]);
                ldmx4(al[mt], sAl_b + aoff[mt][ks]);
            }
#pragma unroll
            for (int ntp = 0; ntp < 4; ntp++) {
                ldmx4(bh[ntp], sBh_b + boff[ntp][ks]);
                ldmx4(bl[ntp], sBl_b + boff[ntp][ks]);
            }
#pragma unroll
            for (int mt = 0; mt < 2; mt++)
#pragma unroll
                for (int nt = 0; nt < 8; nt++) {
                    int p = nt >> 1, hh = (nt & 1) * 2;
                    mma16816(acc[mt][nt], ah[mt], &bh[p][hh]);
                    mma16816(acc[mt][nt], al[mt], &bh[p][hh]);
                    mma16816(acc[mt][nt], ah[mt], &bl[p][hh]);
                }
        }
        buf ^= 1;
        __syncthreads();
    }

    int r0b = rowBase + wm*32 + (lane >> 2);
    int cb  = colBase + wn*64 + (lane & 3)*2;
#pragma unroll
    for (int mt = 0; mt < 2; mt++) {
#pragma unroll
        for (int nt = 0; nt < 8; nt++) {
            int col = cb + nt*8;
#pragma unroll
            for (int half = 0; half < 2; half++) {
                int row = r0b + mt*16 + half*8;
                float vx = acc[mt][nt][half*2+0];
                float vy = acc[mt][nt][half*2+1];
                if (bias) { vx += bias[col]; vy += bias[col+1]; }
                if (MODE == 0 && resid) {
                    const float2 r2 = *(const float2*)(resid + (size_t)row*ldc + col);
                    vx += r2.x; vy += r2.y;
                }
                if (MODE == 0 || MODE == 2) {
                    float2 o; o.x = vx; o.y = vy;
                    *(float2*)(C + (size_t)row*ldc + col) = o;
                }
                if (MODE == 1 || (MODE == 2 && col < DI)) {
                    __nv_bfloat16 hx = __float2bfloat16(vx);
                    __nv_bfloat16 hy = __float2bfloat16(vy);
                    __nv_bfloat162 hv; hv.x = hx; hv.y = hy;
                    __nv_bfloat162 lv;
                    lv.x = __float2bfloat16(vx - __bfloat162float(hx));
                    lv.y = __float2bfloat16(vy - __bfloat162float(hy));
                    *(__nv_bfloat162*)(Ohi + (size_t)row*ldo + col) = hv;
                    *(__nv_bfloat162*)(Olo + (size_t)row*ldo + col) = lv;
                }
            }
        }
    }
}

// ---------------- causal depthwise conv (K=4) + SiLU ----------------
__global__ void conv_kernel(const float* __restrict__ w, const float* __restrict__ bias) {
    int idx = blockIdx.x * blockDim.x + threadIdx.x;
    int c = idx % DI;
    int t = idx / DI;
    int s = t % SS;
    float acc = bias[c];
#pragma unroll
    for (int j = 0; j < KC; j++) {
        int ss = s - 3 + j;
        if (ss >= 0) acc += g_up[(size_t)(t - 3 + j)*2*DI + c] * w[j*DI + c];
    }
    float y = acc / (1.f + __expf(-acc));
    g_xc[idx] = y;
    __nv_bfloat16 h = __float2bfloat16(y);
    g_xc_h[idx] = h;
    g_xc_l[idx] = __float2bfloat16(y - __bfloat162float(h));
}

// ---------------- gate scan: warp-parallel segmented scans ----------------
__global__ void gatescan_kernel() {
    int bh = blockIdx.x;
    int lane = threadIdx.x;
    int b = bh >> 2, h = bh & 3;
    float carryF = 0.f, carryM = -1e30f;
    for (int c = 0; c < SS/32; c++) {
        int t = c*32 + lane;
        const float* gp = g_gates + (size_t)(b*SS + t)*8;
        float fp = gp[NH + h], ipv = gp[h];
        float lf = (fp >= 0.f) ? -log1pf(__expf(-fp)) : fp - log1pf(__expf(fp));
        float s = lf;
#pragma unroll
        for (int d = 1; d < 32; d <<= 1) {
            float v = __shfl_up_sync(0xFFFFFFFFu, s, d);
            if (lane >= d) s += v;
        }
        float Fc = carryF + s;
        float bt = ipv - Fc;
        float mx = bt;
#pragma unroll
        for (int d = 1; d < 32; d <<= 1) {
            float v = __shfl_up_sync(0xFFFFFFFFu, mx, d);
            if (lane >= d) mx = fmaxf(mx, v);
        }
        float rmax = fmaxf(carryM, mx);
        g_beta [bh*SS + t] = bt;
        g_alpha[bh*SS + t] = -rmax;
        g_m    [bh*SS + t] = Fc + rmax;
        carryF += __shfl_sync(0xFFFFFFFFu, s, 31);
        carryM  = fmaxf(carryM, __shfl_sync(0xFFFFFFFFu, rmax, 31));
    }
}

// ================= mma.sync mLSTM attention (reads pre-split bf16) =================
#define STRQ 136
#define STRV 40
#define A2_QH 0
#define A2_QL (A2_QH + 128*STRQ*2)
#define A2_KH (A2_QL + 128*STRQ*2)
#define A2_KL (A2_KH + 32*STRQ*2)
#define A2_VH (A2_KL + 32*STRQ*2)
#define A2_VL (A2_VH + 128*STRV*2)
#define A2_BT (A2_VL + 128*STRV*2)
#define ATTN2_SMEM (A2_BT + 32*4)
#define SCALE 0.08838834764831845f

__global__ void __launch_bounds__(256, 1) attn2_kernel() {
    extern __shared__ char sm2[];
    __nv_bfloat16* Qh = (__nv_bfloat16*)(sm2 + A2_QH);
    __nv_bfloat16* Ql = (__nv_bfloat16*)(sm2 + A2_QL);
    __nv_bfloat16* Kh = (__nv_bfloat16*)(sm2 + A2_KH);
    __nv_bfloat16* Kl = (__nv_bfloat16*)(sm2 + A2_KL);
    __nv_bfloat16* Vh = (__nv_bfloat16*)(sm2 + A2_VH);
    __nv_bfloat16* Vl = (__nv_bfloat16*)(sm2 + A2_VL);
    float* bts = (float*)(sm2 + A2_BT);

    int qt = blockIdx.x, bh = blockIdx.y;
    int b = bh >> 2, h = bh & 3;
    int tid = threadIdx.x, warp = tid >> 5, lane = tid & 31;
    int t0 = qt * 128;

    // load pre-split Q tile (128 x 128 bf16 hi/lo) straight copies
#pragma unroll
    for (int j = 0; j < 8; j++) {
        int i = tid + j*256;                 // 0..2047 uint4 units
        int row = i >> 4, c8 = (i & 15)*8;
        size_t gb = (size_t)(b*SS + t0 + row)*DI + h*DH + c8;
        *(uint4*)(Qh + row*STRQ + c8) = *(const uint4*)(g_qh + gb);
        *(uint4*)(Ql + row*STRQ + c8) = *(const uint4*)(g_ql + gb);
    }

    int tr0 = t0 + warp*16 + (lane >> 2);
    int tr1 = tr0 + 8;
    float al0 = g_alpha[bh*SS + tr0];
    float al1 = g_alpha[bh*SS + tr1];

    float O[16][4];
#pragma unroll
    for (int nt = 0; nt < 16; nt++)
#pragma unroll
        for (int i = 0; i < 4; i++) O[nt][i] = 0.f;
    float rs0 = 0.f, rs1 = 0.f;

    uint32_t sQh = smem_u32(Qh), sQl = smem_u32(Ql);
    uint32_t sKh = smem_u32(Kh), sKl = smem_u32(Kl);
    uint32_t sVh = smem_u32(Vh), sVl = smem_u32(Vl);

    uint32_t qoff[8], koff[2][8], voff[8][2];
#pragma unroll
    for (int ks = 0; ks < 8; ks++)
        qoff[ks] = ((warp*16 + (lane & 15))*STRQ + ks*16 + ((lane >> 4) << 3))*2;
#pragma unroll
    for (int np = 0; np < 2; np++)
#pragma unroll
        for (int ks = 0; ks < 8; ks++)
            koff[np][ks] = ((np*16 + ((lane >> 4) << 3) + (lane & 7))*STRQ
                            + ks*16 + (((lane >> 3) & 1) << 3))*2;
#pragma unroll
    for (int np = 0; np < 8; np++)
#pragma unroll
        for (int kv = 0; kv < 2; kv++)
            voff[np][kv] = ((np*16 + ((lane >> 4) << 3) + (lane & 7))*STRV
                            + kv*16 + (((lane >> 3) & 1) << 3))*2;

    int nst = 4*(qt + 1);
    for (int st = 0; st < nst; st++) {
        int s0 = st * 32;
        __syncthreads();
        // K tile: straight copies; V tile: transpose scatter
#pragma unroll
        for (int j = 0; j < 2; j++) {
            int i = tid + j*256;             // 0..511 uint4 units
            int row = i >> 4, c8 = (i & 15)*8;
            size_t gb = (size_t)(b*SS + s0 + row)*DI + h*DH + c8;
            *(uint4*)(Kh + row*STRQ + c8) = *(const uint4*)(g_kh + gb);
            *(uint4*)(Kl + row*STRQ + c8) = *(const uint4*)(g_kl + gb);
            uint4 vh4 = *(const uint4*)(g_vh + gb);
            uint4 vl4 = *(const uint4*)(g_vl + gb);
            const __nv_bfloat16* vhp = (const __nv_bfloat16*)&vh4;
            const __nv_bfloat16* vlp = (const __nv_bfloat16*)&vl4;
#pragma unroll
            for (int e = 0; e < 8; e++) {
                Vh[(c8+e)*STRV + row] = vhp[e];
                Vl[(c8+e)*STRV + row] = vlp[e];
            }
        }
        if (tid < 32) bts[tid] = g_beta[bh*SS + s0 + tid];
        __syncthreads();

        // ---- S = Q K^T (3-pass split) ----
        float S[4][4];
#pragma unroll
        for (int nt = 0; nt < 4; nt++)
#pragma unroll
            for (int i = 0; i < 4; i++) S[nt][i] = 0.f;
#pragma unroll
        for (int ks = 0; ks < 8; ks++) {
            uint32_t ah[4], al[4], bkh[2][4], bkl[2][4];
            ldmx4(ah, sQh + qoff[ks]);
            ldmx4(al, sQl + qoff[ks]);
            ldmx4(bkh[0], sKh + koff[0][ks]);
            ldmx4(bkh[1], sKh + koff[1][ks]);
            ldmx4(bkl[0], sKl + koff[0][ks]);
            ldmx4(bkl[1], sKl + koff[1][ks]);
#pragma unroll
            for (int nt = 0; nt < 4; nt++) {
                int p = nt >> 1, hh = (nt & 1)*2;
                mma16816(S[nt], ah, &bkh[p][hh]);
                mma16816(S[nt], al, &bkh[p][hh]);
                mma16816(S[nt], ah, &bkl[p][hh]);
            }
        }

        // ---- mask, gate-weight, scale; pack P ----
        uint32_t Ph[2][4], Pl[2][4];
#pragma unroll
        for (int nt = 0; nt < 4; nt++) {
            float pv[4], plv[4];
#pragma unroll
            for (int r = 0; r < 4; r++) {
                int trow = (r < 2) ? tr0 : tr1;
                float alv = (r < 2) ? al0 : al1;
                int cl = nt*8 + (lane & 3)*2 + (r & 1);
                int sc = s0 + cl;
                float w = (sc <= trow) ? __expf(alv + bts[cl]) : 0.f;
                float p = S[nt][r] * SCALE * w;
                if (r < 2) rs0 += p; else rs1 += p;
                pv[r] = p;
                float ph = __bfloat162float(__float2bfloat16(p));
                plv[r] = p - ph;
            }
            int kv = nt >> 1;
            if ((nt & 1) == 0) {
                Ph[kv][0] = packbf2(pv[0], pv[1]);
                Ph[kv][1] = packbf2(pv[2], pv[3]);
                Pl[kv][0] = packbf2(plv[0], plv[1]);
                Pl[kv][1] = packbf2(plv[2], plv[3]);
            } else {
                Ph[kv][2] = packbf2(pv[0], pv[1]);
                Ph[kv][3] = packbf2(pv[2], pv[3]);
                Pl[kv][2] = packbf2(plv[0], plv[1]);
                Pl[kv][3] = packbf2(plv[2], plv[3]);
            }
        }

        // ---- O += P V (3-pass split) ----
#pragma unroll
        for (int kv = 0; kv < 2; kv++) {
#pragma unroll
            for (int np = 0; np < 8; np++) {
                uint32_t bvh[4], bvl[4];
                ldmx4(bvh, sVh + voff[np][kv]);
                ldmx4(bvl, sVl + voff[np][kv]);
#pragma unroll
                for (int hh = 0; hh < 2; hh++) {
                    int nt = np*2 + hh;
                    mma16816(O[nt], Ph[kv], &bvh[hh*2]);
                    mma16816(O[nt], Pl[kv], &bvh[hh*2]);
                    mma16816(O[nt], Ph[kv], &bvl[hh*2]);
                }
            }
        }
    }

    rs0 += __shfl_xor_sync(0xFFFFFFFFu, rs0, 1);
    rs0 += __shfl_xor_sync(0xFFFFFFFFu, rs0, 2);
    rs1 += __shfl_xor_sync(0xFFFFFFFFu, rs1, 1);
    rs1 += __shfl_xor_sync(0xFFFFFFFFu, rs1, 2);
    float me0 = __expf(-g_m[bh*SS + tr0]);
    float me1 = __expf(-g_m[bh*SS + tr1]);
    float inv0 = 1.f / (fmaxf(fabsf(rs0), me0) + 1e-6f);
    float inv1 = 1.f / (fmaxf(fabsf(rs1), me1) + 1e-6f);

    float* o0 = g_ht + (size_t)(b*SS + tr0)*DI + h*DH + (lane & 3)*2;
    float* o1 = g_ht + (size_t)(b*SS + tr1)*DI + h*DH + (lane & 3)*2;
#pragma unroll
    for (int nt = 0; nt < 16; nt++) {
        float2 v0; v0.x = O[nt][0]*inv0; v0.y = O[nt][1]*inv0;
        float2 v1; v1.x = O[nt][2]*inv1; v1.y = O[nt][3]*inv1;
        *(float2*)(o0 + nt*8) = v0;
        *(float2*)(o1 + nt*8) = v1;
    }
}

// ---------------- per-head LN + skip + SiLU(z) gate -> mix hi/lo ----------------
__global__ void gnmerge_kernel(const float* __restrict__ gn_g, const float* __restrict__ gn_b,
                               const float* __restrict__ skip) {
    int t = blockIdx.x, tid = threadIdx.x;
    __shared__ float red[512];
    int l = tid & 127;
    int gbase = (tid >> 7) << 7;
    float v = g_ht[(size_t)t*DI + tid];
    red[tid] = v; __syncthreads();
    for (int off = 64; off > 0; off >>= 1) { if (l < off) red[tid] += red[tid+off]; __syncthreads(); }
    float mean = red[gbase] * (1.f/128.f); __syncthreads();
    float c = v - mean;
    red[tid] = c*c; __syncthreads();
    for (int off = 64; off > 0; off >>= 1) { if (l < off) red[tid] += red[tid+off]; __syncthreads(); }
    float var = red[gbase] * (1.f/128.f);
    float y = c * rsqrtf(var + 1e-5f) * gn_g[tid] + gn_b[tid];
    y += skip[tid] * g_xc[(size_t)t*DI + tid];
    float z = g_up[(size_t)t*2*DI + DI + tid];
    y *= z / (1.f + __expf(-z));
    __nv_bfloat16 hh = __float2bfloat16(y);
    g_mix_h[(size_t)t*DI + tid] = hh;
    g_mix_l[(size_t)t*DI + tid] = __float2bfloat16(y - __bfloat162float(hh));
}

// ---------------- final LN + projection ----------------
__global__ void final_kernel(const float* __restrict__ lnf_g, const float* __restrict__ lnf_b,
                             const float* __restrict__ Wf, const float* __restrict__ bf,
                             float* __restrict__ out) {
    int b = blockIdx.x, tid = threadIdx.x;
    __shared__ float red[256];
    float v = g_h[(size_t)(b*SS + SS - 1)*D + tid];
    red[tid] = v; __syncthreads();
    for (int off = 128; off > 0; off >>= 1) { if (tid < off) red[tid] += red[tid+off]; __syncthreads(); }
    float mean = red[0] * (1.f/256.f); __syncthreads();
    float c = v - mean;
    red[tid] = c*c; __syncthreads();
    for (int off = 128; off > 0; off >>= 1) { if (tid < off) red[tid] += red[tid+off]; __syncthreads(); }
    float var = red[0] * (1.f/256.f); __syncthreads();
    float y = c * rsqrtf(var + 1e-5f) * lnf_g[tid] + lnf_b[tid];
    red[tid] = y * Wf[tid]; __syncthreads();
    for (int off = 128; off > 0; off >>= 1) { if (tid < off) red[tid] += red[tid+off]; __syncthreads(); }
    if (tid == 0) out[b] = red[0] + bf[0];
}

// ---------------- host ----------------
static float* symaddrf(const void* sym) {
    void* p = nullptr;
    cudaGetSymbolAddress(&p, sym);
    return (float*)p;
}
static __nv_bfloat16* symaddrb(const void* sym) {
    void* p = nullptr;
    cudaGetSymbolAddress(&p, sym);
    return (__nv_bfloat16*)p;
}

extern "C" void kernel_launch(void* const* d_in, const int* in_sizes, int n_in,
                              void* d_out, int out_size) {
    const float* x      = (const float*)d_in[0];
    const float* tf     = (const float*)d_in[1];
    const float* Wp     = (const float*)d_in[2];
    const float* bp     = (const float*)d_in[3];
    const float* ln_g   = (const float*)d_in[4];
    const float* ln_b   = (const float*)d_in[5];
    const float* Wup    = (const float*)d_in[6];
    const float* bup    = (const float*)d_in[7];
    const float* conv_w = (const float*)d_in[8];
    const float* conv_b = (const float*)d_in[9];
    const float* Wq     = (const float*)d_in[10];
    const float* Wk     = (const float*)d_in[11];
    const float* Wv     = (const float*)d_in[12];
    const float* Wif    = (const float*)d_in[13];
    const float* bif    = (const float*)d_in[14];
    const float* gn_g   = (const float*)d_in[15];
    const float* gn_b   = (const float*)d_in[16];
    const float* skip   = (const float*)d_in[17];
    const float* Wdown  = (const float*)d_in[18];
    const float* bdown  = (const float*)d_in[19];
    const float* lnf_g  = (const float*)d_in[20];
    const float* lnf_b  = (const float*)d_in[21];
    const float* Wf     = (const float*)d_in[22];
    const float* bf     = (const float*)d_in[23];
    float* out = (float*)d_out;

    float* p_h   = symaddrf(g_h);
    float* p_up  = symaddrf(g_up);
    float* p_wc  = symaddrf(g_wc);
    __nv_bfloat16* p_hn_h = symaddrb(g_hn_h);
    __nv_bfloat16* p_hn_l = symaddrb(g_hn_l);
    __nv_bfloat16* p_xc_h = symaddrb(g_xc_h);
    __nv_bfloat16* p_xc_l = symaddrb(g_xc_l);
    __nv_bfloat16* p_xm_h = symaddrb(g_xm_h);
    __nv_bfloat16* p_xm_l = symaddrb(g_xm_l);
    __nv_bfloat16* p_mix_h = symaddrb(g_mix_h);
    __nv_bfloat16* p_mix_l = symaddrb(g_mix_l);
    __nv_bfloat16* p_wt_h = symaddrb(g_wt_h);
    __nv_bfloat16* p_wt_l = symaddrb(g_wt_l);
    __nv_bfloat16* p_qh = symaddrb(g_qh);
    __nv_bfloat16* p_ql = symaddrb(g_ql);
    __nv_bfloat16* p_kh = symaddrb(g_kh);
    __nv_bfloat16* p_kl = symaddrb(g_kl);
    __nv_bfloat16* p_vh = symaddrb(g_vh);
    __nv_bfloat16* p_vl = symaddrb(g_vl);

    cudaFuncSetAttribute(attn2_kernel, cudaFuncAttributeMaxDynamicSharedMemorySize, ATTN2_SMEM);
    cudaFuncSetAttribute(mmagemm2_kernel<0>, cudaFuncAttributeMaxDynamicSharedMemorySize, GEMM_SMEM);
    cudaFuncSetAttribute(mmagemm2_kernel<1>, cudaFuncAttributeMaxDynamicSharedMemorySize, GEMM_SMEM);
    cudaFuncSetAttribute(mmagemm2_kernel<2>, cudaFuncAttributeMaxDynamicSharedMemorySize, GEMM_SMEM);

    // weight prep (all layers)
    dim3 wblk(32, 8);
    for (int l = 0; l < NL; l++) {
        size_t wo = (size_t)l * WT_L;
        wsplit_kernel<<<dim3(D/32, 2*DI/32), wblk>>>(Wup + (size_t)l*D*2*DI, D, 2*DI,
                                                     p_wt_h + wo + WT_UP_OFF, p_wt_l + wo + WT_UP_OFF);
        wsplit_kernel<<<dim3(DI/32, DI/32), wblk>>>(Wq + (size_t)l*DI*DI, DI, DI,
                                                    p_wt_h + wo + WT_Q_OFF, p_wt_l + wo + WT_Q_OFF);
        wsplit_kernel<<<dim3(DI/32, DI/32), wblk>>>(Wk + (size_t)l*DI*DI, DI, DI,
                                                    p_wt_h + wo + WT_K_OFF, p_wt_l + wo + WT_K_OFF);
        wsplit_kernel<<<dim3(DI/32, DI/32), wblk>>>(Wv + (size_t)l*DI*DI, DI, DI,
                                                    p_wt_h + wo + WT_V_OFF, p_wt_l + wo + WT_V_OFF);
        wsplit_kernel<<<dim3(DI/32, D/32), wblk>>>(Wdown + (size_t)l*DI*D, DI, D,
                                                   p_wt_h + wo + WT_DN_OFF, p_wt_l + wo + WT_DN_OFF);
        wcomb_kernel<<<DI, 256>>>(Wq + (size_t)l*DI*DI, Wk + (size_t)l*DI*DI,
                                  Wv + (size_t)l*DI*DI, Wif + (size_t)l*3*DI*8,
                                  p_wc + (size_t)l*DI*16);
    }

    embed_kernel<<<NT, 256>>>(x, tf, Wp, bp);

    for (int l = 0; l < NL; l++) {
        size_t wo = (size_t)l * WT_L;
        ln256_kernel<<<NT, 256>>>(p_h, ln_g + l*D, ln_b + l*D);

        // up: fp32 out + xm split (cols<512)
        mmagemm2_kernel<2><<<dim3(NT/128, 1024/128), 256, GEMM_SMEM>>>(
            p_hn_h, p_hn_l, D, p_wt_h + wo + WT_UP_OFF, p_wt_l + wo + WT_UP_OFF,
            bup + l*2*DI, nullptr, p_up, 2*DI, p_xm_h, p_xm_l, DI, D);

        conv_kernel<<<NT*DI/256, 256>>>(conv_w + l*KC*DI, conv_b + l*DI);

        mmagemm2_kernel<1><<<dim3(NT/128, DI/128), 256, GEMM_SMEM>>>(
            p_xc_h, p_xc_l, DI, p_wt_h + wo + WT_Q_OFF, p_wt_l + wo + WT_Q_OFF,
            nullptr, nullptr, nullptr, 0, p_qh, p_ql, DI, DI);
        mmagemm2_kernel<1><<<dim3(NT/128, DI/128), 256, GEMM_SMEM>>>(
            p_xc_h, p_xc_l, DI, p_wt_h + wo + WT_K_OFF, p_wt_l + wo + WT_K_OFF,
            nullptr, nullptr, nullptr, 0, p_kh, p_kl, DI, DI);
        mmagemm2_kernel<1><<<dim3(NT/128, DI/128), 256, GEMM_SMEM>>>(
            p_xm_h, p_xm_l, DI, p_wt_h + wo + WT_V_OFF, p_wt_l + wo + WT_V_OFF,
            nullptr, nullptr, nullptr, 0, p_vh, p_vl, DI, DI);

        gates2_kernel<<<NT/8, 256>>>(p_wc + (size_t)l*DI*16, bif + l*2*NH);
        gatescan_kernel<<<NBH, 32>>>();

        attn2_kernel<<<dim3(SS/128, NBH), 256, ATTN2_SMEM>>>();

        gnmerge_kernel<<<NT, 512>>>(gn_g + l*DI, gn_b + l*DI, skip + l*DI);

        mmagemm2_kernel<0><<<dim3(NT/128, D/128), 256, GEMM_SMEM>>>(
            p_mix_h, p_mix_l, DI, p_wt_h + wo + WT_DN_OFF, p_wt_l + wo + WT_DN_OFF,
            bdown + l*D, p_h, p_h, D, nullptr, nullptr, 0, DI);
    }

    final_kernel<<<NB, 256>>>(lnf_g, lnf_b, Wf, bf, out);
}

// round 6
// speedup vs baseline: 5.6149x; 1.3733x over previous
#include <cuda_runtime.h>
#include <cuda_fp16.h>
#include <math.h>
#include <stdint.h>

#define D   256
#define DI  512
#define NH  4
#define DH  128
#define NL  4
#define KC  4
#define NB  8
#define SS  1024
#define NT  (NB*SS)
#define NBH (NB*NH)

// ---------------- scratch ----------------
__device__ float g_h [NT*D];
__device__ float g_up[NT*2*DI];
__device__ float g_xc[NT*DI];
__device__ float g_ht[NT*DI];
__device__ float g_gates[NT*2*NH];
__device__ float g_alpha[NBH*SS];
__device__ float g_beta [NBH*SS];
__device__ float g_m    [NBH*SS];
__device__ float g_wc   [NL*DI*16];

// fp16 split activations (hi/lo where needed, hi-only otherwise)
__device__ __half g_hn_h[NT*D],  g_hn_l[NT*D];
__device__ __half g_xc_h[NT*DI], g_xc_l[NT*DI];
__device__ __half g_xm_h[NT*DI], g_xm_l[NT*DI];
__device__ __half g_mix_h[NT*DI], g_mix_l[NT*DI];
__device__ __half g_qh[NT*DI], g_ql[NT*DI];
__device__ __half g_kh[NT*DI];
__device__ __half g_vh[NT*DI];

// fp16 transposed weights [N,K] per layer (hi only)
#define WT_UP_OFF   0
#define WT_Q_OFF    262144
#define WT_K_OFF    524288
#define WT_V_OFF    786432
#define WT_DN_OFF   1048576
#define WT_L        1179648
__device__ __half g_wt_h[NL*WT_L];

__device__ __forceinline__ uint32_t smem_u32(const void* p) {
    uint32_t a;
    asm("{ .reg .u64 t; cvta.to.shared.u64 t, %1; cvt.u32.u64 %0, t; }" : "=r"(a) : "l"(p));
    return a;
}
__device__ __forceinline__ void ldmx4(uint32_t* r, uint32_t addr) {
    asm volatile("ldmatrix.sync.aligned.m8n8.x4.shared.b16 {%0,%1,%2,%3}, [%4];"
        : "=r"(r[0]), "=r"(r[1]), "=r"(r[2]), "=r"(r[3]) : "r"(addr));
}
__device__ __forceinline__ void mma16816(float* d, const uint32_t* a, const uint32_t* b) {
    asm volatile(
        "mma.sync.aligned.m16n8k16.row.col.f32.f16.f16.f32 "
        "{%0,%1,%2,%3}, {%4,%5,%6,%7}, {%8,%9}, {%0,%1,%2,%3};"
        : "+f"(d[0]), "+f"(d[1]), "+f"(d[2]), "+f"(d[3])
        : "r"(a[0]), "r"(a[1]), "r"(a[2]), "r"(a[3]), "r"(b[0]), "r"(b[1]));
}
__device__ __forceinline__ uint32_t packh2(float lo, float hi) {
    __half2 p = __floats2half2_rn(lo, hi);
    return *(uint32_t*)&p;
}
__device__ __forceinline__ void cpa16(uint32_t s, const void* g) {
    asm volatile("cp.async.cg.shared.global [%0], [%1], 16;" :: "r"(s), "l"(g));
}
#define CP_COMMIT() asm volatile("cp.async.commit_group;" ::: "memory")
#define CP_WAIT0()  asm volatile("cp.async.wait_group 0;" ::: "memory")

// ---------------- embed ----------------
__global__ void embed_kernel(const float* __restrict__ x, const float* __restrict__ tf,
                             const float* __restrict__ Wp, const float* __restrict__ bp) {
    int t = blockIdx.x, d = threadIdx.x;
    float acc = bp[d] + x[t] * Wp[d];
#pragma unroll
    for (int j = 0; j < 4; j++) acc += tf[t*4 + j] * Wp[(1+j)*D + d];
    g_h[t*D + d] = acc;
}

// ---------------- LayerNorm over D=256 -> fp16 hi/lo ----------------
__global__ void ln256_kernel(const float* __restrict__ in, const float* __restrict__ g,
                             const float* __restrict__ b) {
    int t = blockIdx.x, tid = threadIdx.x;
    __shared__ float red[256];
    float v = in[t*256 + tid];
    red[tid] = v; __syncthreads();
    for (int off = 128; off > 0; off >>= 1) { if (tid < off) red[tid] += red[tid+off]; __syncthreads(); }
    float mean = red[0] * (1.f/256.f); __syncthreads();
    float c = v - mean;
    red[tid] = c*c; __syncthreads();
    for (int off = 128; off > 0; off >>= 1) { if (tid < off) red[tid] += red[tid+off]; __syncthreads(); }
    float var = red[0] * (1.f/256.f);
    float y = c * rsqrtf(var + 1e-5f) * g[tid] + b[tid];
    __half h = __float2half_rn(y);
    g_hn_h[t*256 + tid] = h;
    g_hn_l[t*256 + tid] = __float2half_rn(y - __half2float(h));
}

// ---------------- batched weight transpose: W[l] (KxN) -> Wt fp16 (NxK) ----------------
__global__ void wsplit_all(const float* __restrict__ Wbase, long wstride, int K, int N,
                           __half* __restrict__ th, long ostride) {
    __shared__ float tile[32][33];
    int l = blockIdx.z;
    const float* W = Wbase + (size_t)l*wstride;
    __half* out = th + (size_t)l*ostride;
    int k0 = blockIdx.x*32, n0 = blockIdx.y*32;
    int tx = threadIdx.x, ty = threadIdx.y;
    for (int i = ty; i < 32; i += 8)
        tile[i][tx] = W[(size_t)(k0+i)*N + n0 + tx];
    __syncthreads();
    for (int i = ty; i < 32; i += 8)
        out[(size_t)(n0+i)*K + k0 + tx] = __float2half_rn(tile[tx][i]);
}

// ---------------- combined gate weights (all layers) ----------------
__global__ void wcomb_kernel(const float* __restrict__ Wq0, const float* __restrict__ Wk0,
                             const float* __restrict__ Wv0, const float* __restrict__ Wif0,
                             float* __restrict__ wc0) {
    int i = blockIdx.x, l = blockIdx.y;
    const float* Wq = Wq0 + (size_t)l*DI*DI;
    const float* Wk = Wk0 + (size_t)l*DI*DI;
    const float* Wv = Wv0 + (size_t)l*DI*DI;
    const float* Wif = Wif0 + (size_t)l*3*DI*8;
    float* wc = wc0 + (size_t)l*DI*16;
    int warp = threadIdx.x >> 5, lane = threadIdx.x & 31;
    float a1 = 0.f, a2 = 0.f;
    for (int j = lane; j < DI; j += 32) {
        a1 += Wq[(size_t)i*DI + j] * Wif[j*8 + warp]
            + Wk[(size_t)i*DI + j] * Wif[(DI + j)*8 + warp];
        a2 += Wv[(size_t)i*DI + j] * Wif[(2*DI + j)*8 + warp];
    }
#pragma unroll
    for (int d = 16; d > 0; d >>= 1) {
        a1 += __shfl_xor_sync(0xFFFFFFFFu, a1, d);
        a2 += __shfl_xor_sync(0xFFFFFFFFu, a2, d);
    }
    if (lane == 0) {
        wc[i*16 + warp] = a1;
        wc[i*16 + 8 + warp] = a2;
    }
}

// ---------------- gates: gates[t] = xc[t]@W1 + xm[t]@W2 + bif ----------------
__global__ void gates2_kernel(const float* __restrict__ wc, const float* __restrict__ bif) {
    int warp = threadIdx.x >> 5, lane = threadIdx.x & 31;
    int t = blockIdx.x*8 + warp;
    float acc[8];
#pragma unroll
    for (int g = 0; g < 8; g++) acc[g] = 0.f;
    const float* xcr = g_xc + (size_t)t*DI;
    const float* xmr = g_up + (size_t)t*2*DI;
    for (int j = lane; j < DI; j += 32) {
        float xcv = xcr[j], xmv = xmr[j];
        const float* w = wc + j*16;
#pragma unroll
        for (int g = 0; g < 8; g++) acc[g] += xcv*w[g] + xmv*w[8+g];
    }
#pragma unroll
    for (int g = 0; g < 8; g++) {
#pragma unroll
        for (int d = 16; d > 0; d >>= 1) acc[g] += __shfl_xor_sync(0xFFFFFFFFu, acc[g], d);
    }
    if (lane < 8) g_gates[(size_t)t*8 + lane] = acc[lane] + bif[lane];
}

// ================= cp.async double-buffered fp16 2-pass GEMM =================
// C(MxN) = (Ah+Al)(MxK) @ B^T,  B stored [N,K] fp16 single.
#define TSTR 40
#define OFF_AH 0
#define OFF_AL 10240
#define OFF_BH 20480
#define STAGE_B 30720
#define GEMM_SMEM (2*STAGE_B)

// MODE: 0 fp32 (+bias,+resid) | 1 fp16 hi/lo | 2 fp32 + hi/lo for col<DI | 3 fp16 hi only
template<int MODE>
__global__ void __launch_bounds__(256)
mmagemm2_kernel(const __half* __restrict__ Ah, const __half* __restrict__ Al, int lda,
                const __half* __restrict__ Bh,
                const float* __restrict__ bias, const float* __restrict__ resid,
                float* __restrict__ C, int ldc,
                __half* __restrict__ Ohi, __half* __restrict__ Olo, int ldo,
                int K) {
    extern __shared__ char dsm[];
    uint32_t sb = smem_u32(dsm);

    int tid = threadIdx.x;
    int warp = tid >> 5, lane = tid & 31;
    int wm = warp >> 1, wn = warp & 1;
    int rowBase = blockIdx.x * 128;
    int colBase = blockIdx.y * 128;

    const __half* Ah0 = Ah + (size_t)rowBase*lda;
    const __half* Al0 = Al + (size_t)rowBase*lda;
    const __half* Bh0 = Bh + (size_t)colBase*K;

    float acc[2][8][4];
#pragma unroll
    for (int mt = 0; mt < 2; mt++)
#pragma unroll
        for (int nt = 0; nt < 8; nt++)
#pragma unroll
            for (int i = 0; i < 4; i++) acc[mt][nt][i] = 0.f;

    uint32_t aoff[2][2], boff[4][2];
#pragma unroll
    for (int mt = 0; mt < 2; mt++)
#pragma unroll
        for (int ks = 0; ks < 2; ks++)
            aoff[mt][ks] = ((wm*32 + mt*16 + (lane & 15))*TSTR + ks*16 + ((lane >> 4) << 3))*2;
#pragma unroll
    for (int ntp = 0; ntp < 4; ntp++)
#pragma unroll
        for (int ks = 0; ks < 2; ks++)
            boff[ntp][ks] = ((wn*64 + ntp*16 + ((lane >> 4) << 3) + (lane & 7))*TSTR
                             + ks*16 + (((lane >> 3) & 1) << 3))*2;

    int ldRow = tid >> 2, ldQuad = tid & 3;
    uint32_t soA = (ldRow*TSTR + ldQuad*8)*2;
    uint32_t soB = ((ldRow+64)*TSTR + ldQuad*8)*2;

    int nch = K >> 5;
    {
        uint32_t st = sb;
        cpa16(st + OFF_AH + soA, Ah0 + (size_t)ldRow*lda + ldQuad*8);
        cpa16(st + OFF_AL + soA, Al0 + (size_t)ldRow*lda + ldQuad*8);
        cpa16(st + OFF_BH + soA, Bh0 + (size_t)ldRow*K + ldQuad*8);
        cpa16(st + OFF_AH + soB, Ah0 + (size_t)(ldRow+64)*lda + ldQuad*8);
        cpa16(st + OFF_AL + soB, Al0 + (size_t)(ldRow+64)*lda + ldQuad*8);
        cpa16(st + OFF_BH + soB, Bh0 + (size_t)(ldRow+64)*K + ldQuad*8);
        CP_COMMIT();
    }

    int buf = 0;
    for (int ch = 0; ch < nch; ch++) {
        CP_WAIT0();
        __syncthreads();
        if (ch + 1 < nch) {
            int k1 = (ch + 1) << 5;
            uint32_t st = sb + (buf ^ 1)*STAGE_B;
            cpa16(st + OFF_AH + soA, Ah0 + (size_t)ldRow*lda + k1 + ldQuad*8);
            cpa16(st + OFF_AL + soA, Al0 + (size_t)ldRow*lda + k1 + ldQuad*8);
            cpa16(st + OFF_BH + soA, Bh0 + (size_t)ldRow*K + k1 + ldQuad*8);
            cpa16(st + OFF_AH + soB, Ah0 + (size_t)(ldRow+64)*lda + k1 + ldQuad*8);
            cpa16(st + OFF_AL + soB, Al0 + (size_t)(ldRow+64)*lda + k1 + ldQuad*8);
            cpa16(st + OFF_BH + soB, Bh0 + (size_t)(ldRow+64)*K + k1 + ldQuad*8);
            CP_COMMIT();
        }
        uint32_t st = sb + buf*STAGE_B;
        uint32_t sAh_b = st + OFF_AH, sAl_b = st + OFF_AL, sBh_b = st + OFF_BH;
#pragma unroll
        for (int ks = 0; ks < 2; ks++) {
            uint32_t ah[2][4], al[2][4], bh[4][4];
#pragma unroll
            for (int mt = 0; mt < 2; mt++) {
                ldmx4(ah[mt], sAh_b + aoff[mt][ks]);
                ldmx4(al[mt], sAl_b + aoff[mt][ks]);
            }
#pragma unroll
            for (int ntp = 0; ntp < 4; ntp++)
                ldmx4(bh[ntp], sBh_b + boff[ntp][ks]);
#pragma unroll
            for (int mt = 0; mt < 2; mt++)
#pragma unroll
                for (int nt = 0; nt < 8; nt++) {
                    int p = nt >> 1, hh = (nt & 1) * 2;
                    mma16816(acc[mt][nt], ah[mt], &bh[p][hh]);
                    mma16816(acc[mt][nt], al[mt], &bh[p][hh]);
                }
        }
        buf ^= 1;
        __syncthreads();
    }

    int r0b = rowBase + wm*32 + (lane >> 2);
    int cb  = colBase + wn*64 + (lane & 3)*2;
#pragma unroll
    for (int mt = 0; mt < 2; mt++) {
#pragma unroll
        for (int nt = 0; nt < 8; nt++) {
            int col = cb + nt*8;
#pragma unroll
            for (int half = 0; half < 2; half++) {
                int row = r0b + mt*16 + half*8;
                float vx = acc[mt][nt][half*2+0];
                float vy = acc[mt][nt][half*2+1];
                if (bias) { vx += bias[col]; vy += bias[col+1]; }
                if (MODE == 0 && resid) {
                    const float2 r2 = *(const float2*)(resid + (size_t)row*ldc + col);
                    vx += r2.x; vy += r2.y;
                }
                if (MODE == 0 || MODE == 2) {
                    float2 o; o.x = vx; o.y = vy;
                    *(float2*)(C + (size_t)row*ldc + col) = o;
                }
                if (MODE == 1 || MODE == 3 || (MODE == 2 && col < DI)) {
                    __half hx = __float2half_rn(vx);
                    __half hy = __float2half_rn(vy);
                    __half2 hv; hv.x = hx; hv.y = hy;
                    *(__half2*)(Ohi + (size_t)row*ldo + col) = hv;
                    if (MODE != 3) {
                        __half2 lv;
                        lv.x = __float2half_rn(vx - __half2float(hx));
                        lv.y = __float2half_rn(vy - __half2float(hy));
                        *(__half2*)(Olo + (size_t)row*ldo + col) = lv;
                    }
                }
            }
        }
    }
}

// ---------------- causal depthwise conv (K=4) + SiLU ----------------
__global__ void conv_kernel(const float* __restrict__ w, const float* __restrict__ bias) {
    int idx = blockIdx.x * blockDim.x + threadIdx.x;
    int c = idx % DI;
    int t = idx / DI;
    int s = t % SS;
    float acc = bias[c];
#pragma unroll
    for (int j = 0; j < KC; j++) {
        int ss = s - 3 + j;
        if (ss >= 0) acc += g_up[(size_t)(t - 3 + j)*2*DI + c] * w[j*DI + c];
    }
    float y = acc / (1.f + __expf(-acc));
    g_xc[idx] = y;
    __half h = __float2half_rn(y);
    g_xc_h[idx] = h;
    g_xc_l[idx] = __float2half_rn(y - __half2float(h));
}

// ---------------- gate scan ----------------
__global__ void gatescan_kernel() {
    int bh = blockIdx.x;
    int lane = threadIdx.x;
    int b = bh >> 2, h = bh & 3;
    float carryF = 0.f, carryM = -1e30f;
    for (int c = 0; c < SS/32; c++) {
        int t = c*32 + lane;
        const float* gp = g_gates + (size_t)(b*SS + t)*8;
        float fp = gp[NH + h], ipv = gp[h];
        float lf = (fp >= 0.f) ? -log1pf(__expf(-fp)) : fp - log1pf(__expf(fp));
        float s = lf;
#pragma unroll
        for (int d = 1; d < 32; d <<= 1) {
            float v = __shfl_up_sync(0xFFFFFFFFu, s, d);
            if (lane >= d) s += v;
        }
        float Fc = carryF + s;
        float bt = ipv - Fc;
        float mx = bt;
#pragma unroll
        for (int d = 1; d < 32; d <<= 1) {
            float v = __shfl_up_sync(0xFFFFFFFFu, mx, d);
            if (lane >= d) mx = fmaxf(mx, v);
        }
        float rmax = fmaxf(carryM, mx);
        g_beta [bh*SS + t] = bt;
        g_alpha[bh*SS + t] = -rmax;
        g_m    [bh*SS + t] = Fc + rmax;
        carryF += __shfl_sync(0xFFFFFFFFu, s, 31);
        carryM  = fmaxf(carryM, __shfl_sync(0xFFFFFFFFu, rmax, 31));
    }
}

// ================= fp16 2-pass mLSTM attention =================
#define STRQ 136
#define STRV 40
#define A2_QH 0
#define A2_QL (A2_QH + 128*STRQ*2)
#define A2_KH (A2_QL + 128*STRQ*2)
#define A2_VH (A2_KH + 32*STRQ*2)
#define A2_BT (A2_VH + 128*STRV*2)
#define ATTN2_SMEM (A2_BT + 32*4)
#define SCALE 0.08838834764831845f

__global__ void __launch_bounds__(256) attn2_kernel() {
    extern __shared__ char sm2[];
    __half* Qh = (__half*)(sm2 + A2_QH);
    __half* Ql = (__half*)(sm2 + A2_QL);
    __half* Kh = (__half*)(sm2 + A2_KH);
    __half* Vh = (__half*)(sm2 + A2_VH);
    float* bts = (float*)(sm2 + A2_BT);

    int qt = blockIdx.x, bh = blockIdx.y;
    int b = bh >> 2, h = bh & 3;
    int tid = threadIdx.x, warp = tid >> 5, lane = tid & 31;
    int t0 = qt * 128;

#pragma unroll
    for (int j = 0; j < 8; j++) {
        int i = tid + j*256;
        int row = i >> 4, c8 = (i & 15)*8;
        size_t gb = (size_t)(b*SS + t0 + row)*DI + h*DH + c8;
        *(uint4*)(Qh + row*STRQ + c8) = *(const uint4*)(g_qh + gb);
        *(uint4*)(Ql + row*STRQ + c8) = *(const uint4*)(g_ql + gb);
    }

    int tr0 = t0 + warp*16 + (lane >> 2);
    int tr1 = tr0 + 8;
    float al0 = g_alpha[bh*SS + tr0];
    float al1 = g_alpha[bh*SS + tr1];

    float O[16][4];
#pragma unroll
    for (int nt = 0; nt < 16; nt++)
#pragma unroll
        for (int i = 0; i < 4; i++) O[nt][i] = 0.f;
    float rs0 = 0.f, rs1 = 0.f;

    uint32_t sQh = smem_u32(Qh), sQl = smem_u32(Ql);
    uint32_t sKh = smem_u32(Kh), sVh = smem_u32(Vh);

    uint32_t qoff[8], koff[2][8], voff[8][2];
#pragma unroll
    for (int ks = 0; ks < 8; ks++)
        qoff[ks] = ((warp*16 + (lane & 15))*STRQ + ks*16 + ((lane >> 4) << 3))*2;
#pragma unroll
    for (int np = 0; np < 2; np++)
#pragma unroll
        for (int ks = 0; ks < 8; ks++)
            koff[np][ks] = ((np*16 + ((lane >> 4) << 3) + (lane & 7))*STRQ
                            + ks*16 + (((lane >> 3) & 1) << 3))*2;
#pragma unroll
    for (int np = 0; np < 8; np++)
#pragma unroll
        for (int kv = 0; kv < 2; kv++)
            voff[np][kv] = ((np*16 + ((lane >> 4) << 3) + (lane & 7))*STRV
                            + kv*16 + (((lane >> 3) & 1) << 3))*2;

    int nst = 4*(qt + 1);
    for (int st = 0; st < nst; st++) {
        int s0 = st * 32;
        __syncthreads();
#pragma unroll
        for (int j = 0; j < 2; j++) {
            int i = tid + j*256;
            int row = i >> 4, c8 = (i & 15)*8;
            size_t gb = (size_t)(b*SS + s0 + row)*DI + h*DH + c8;
            *(uint4*)(Kh + row*STRQ + c8) = *(const uint4*)(g_kh + gb);
            uint4 vh4 = *(const uint4*)(g_vh + gb);
            const __half* vhp = (const __half*)&vh4;
#pragma unroll
            for (int e = 0; e < 8; e++)
                Vh[(c8+e)*STRV + row] = vhp[e];
        }
        if (tid < 32) bts[tid] = g_beta[bh*SS + s0 + tid];
        __syncthreads();

        // ---- S = (Qh+Ql) Kh^T ----
        float S[4][4];
#pragma unroll
        for (int nt = 0; nt < 4; nt++)
#pragma unroll
            for (int i = 0; i < 4; i++) S[nt][i] = 0.f;
#pragma unroll
        for (int ks = 0; ks < 8; ks++) {
            uint32_t ah[4], al[4], bkh[2][4];
            ldmx4(ah, sQh + qoff[ks]);
            ldmx4(al, sQl + qoff[ks]);
            ldmx4(bkh[0], sKh + koff[0][ks]);
            ldmx4(bkh[1], sKh + koff[1][ks]);
#pragma unroll
            for (int nt = 0; nt < 4; nt++) {
                int p = nt >> 1, hh = (nt & 1)*2;
                mma16816(S[nt], ah, &bkh[p][hh]);
                mma16816(S[nt], al, &bkh[p][hh]);
            }
        }

        // ---- mask, gate-weight, scale; pack P hi/lo ----
        uint32_t Ph[2][4], Pl[2][4];
#pragma unroll
        for (int nt = 0; nt < 4; nt++) {
            float pv[4], plv[4];
#pragma unroll
            for (int r = 0; r < 4; r++) {
                int trow = (r < 2) ? tr0 : tr1;
                float alv = (r < 2) ? al0 : al1;
                int cl = nt*8 + (lane & 3)*2 + (r & 1);
                int sc = s0 + cl;
                float w = (sc <= trow) ? __expf(alv + bts[cl]) : 0.f;
                float p = S[nt][r] * SCALE * w;
                if (r < 2) rs0 += p; else rs1 += p;
                pv[r] = p;
                float ph = __half2float(__float2half_rn(p));
                plv[r] = p - ph;
            }
            int kv = nt >> 1;
            if ((nt & 1) == 0) {
                Ph[kv][0] = packh2(pv[0], pv[1]);
                Ph[kv][1] = packh2(pv[2], pv[3]);
                Pl[kv][0] = packh2(plv[0], plv[1]);
                Pl[kv][1] = packh2(plv[2], plv[3]);
            } else {
                Ph[kv][2] = packh2(pv[0], pv[1]);
                Ph[kv][3] = packh2(pv[2], pv[3]);
                Pl[kv][2] = packh2(plv[0], plv[1]);
                Pl[kv][3] = packh2(plv[2], plv[3]);
            }
        }

        // ---- O += (Ph+Pl) Vh ----
#pragma unroll
        for (int kv = 0; kv < 2; kv++) {
#pragma unroll
            for (int np = 0; np < 8; np++) {
                uint32_t bvh[4];
                ldmx4(bvh, sVh + voff[np][kv]);
#pragma unroll
                for (int hh = 0; hh < 2; hh++) {
                    int nt = np*2 + hh;
                    mma16816(O[nt], Ph[kv], &bvh[hh*2]);
                    mma16816(O[nt], Pl[kv], &bvh[hh*2]);
                }
            }
        }
    }

    rs0 += __shfl_xor_sync(0xFFFFFFFFu, rs0, 1);
    rs0 += __shfl_xor_sync(0xFFFFFFFFu, rs0, 2);
    rs1 += __shfl_xor_sync(0xFFFFFFFFu, rs1, 1);
    rs1 += __shfl_xor_sync(0xFFFFFFFFu, rs1, 2);
    float me0 = __expf(-g_m[bh*SS + tr0]);
    float me1 = __expf(-g_m[bh*SS + tr1]);
    float inv0 = 1.f / (fmaxf(fabsf(rs0), me0) + 1e-6f);
    float inv1 = 1.f / (fmaxf(fabsf(rs1), me1) + 1e-6f);

    float* o0 = g_ht + (size_t)(b*SS + tr0)*DI + h*DH + (lane & 3)*2;
    float* o1 = g_ht + (size_t)(b*SS + tr1)*DI + h*DH + (lane & 3)*2;
#pragma unroll
    for (int nt = 0; nt < 16; nt++) {
        float2 v0; v0.x = O[nt][0]*inv0; v0.y = O[nt][1]*inv0;
        float2 v1; v1.x = O[nt][2]*inv1; v1.y = O[nt][3]*inv1;
        *(float2*)(o0 + nt*8) = v0;
        *(float2*)(o1 + nt*8) = v1;
    }
}

// ---------------- per-head LN + skip + SiLU(z) gate -> mix hi/lo ----------------
__global__ void gnmerge_kernel(const float* __restrict__ gn_g, const float* __restrict__ gn_b,
                               const float* __restrict__ skip) {
    int t = blockIdx.x, tid = threadIdx.x;
    __shared__ float red[512];
    int l = tid & 127;
    int gbase = (tid >> 7) << 7;
    float v = g_ht[(size_t)t*DI + tid];
    red[tid] = v; __syncthreads();
    for (int off = 64; off > 0; off >>= 1) { if (l < off) red[tid] += red[tid+off]; __syncthreads(); }
    float mean = red[gbase] * (1.f/128.f); __syncthreads();
    float c = v - mean;
    red[tid] = c*c; __syncthreads();
    for (int off = 64; off > 0; off >>= 1) { if (l < off) red[tid] += red[tid+off]; __syncthreads(); }
    float var = red[gbase] * (1.f/128.f);
    float y = c * rsqrtf(var + 1e-5f) * gn_g[tid] + gn_b[tid];
    y += skip[tid] * g_xc[(size_t)t*DI + tid];
    float z = g_up[(size_t)t*2*DI + DI + tid];
    y *= z / (1.f + __expf(-z));
    __half hh = __float2half_rn(y);
    g_mix_h[(size_t)t*DI + tid] = hh;
    g_mix_l[(size_t)t*DI + tid] = __float2half_rn(y - __half2float(hh));
}

// ---------------- final LN + projection ----------------
__global__ void final_kernel(const float* __restrict__ lnf_g, const float* __restrict__ lnf_b,
                             const float* __restrict__ Wf, const float* __restrict__ bf,
                             float* __restrict__ out) {
    int b = blockIdx.x, tid = threadIdx.x;
    __shared__ float red[256];
    float v = g_h[(size_t)(b*SS + SS - 1)*D + tid];
    red[tid] = v; __syncthreads();
    for (int off = 128; off > 0; off >>= 1) { if (tid < off) red[tid] += red[tid+off]; __syncthreads(); }
    float mean = red[0] * (1.f/256.f); __syncthreads();
    float c = v - mean;
    red[tid] = c*c; __syncthreads();
    for (int off = 128; off > 0; off >>= 1) { if (tid < off) red[tid] += red[tid+off]; __syncthreads(); }
    float var = red[0] * (1.f/256.f); __syncthreads();
    float y = c * rsqrtf(var + 1e-5f) * lnf_g[tid] + lnf_b[tid];
    red[tid] = y * Wf[tid]; __syncthreads();
    for (int off = 128; off > 0; off >>= 1) { if (tid < off) red[tid] += red[tid+off]; __syncthreads(); }
    if (tid == 0) out[b] = red[0] + bf[0];
}

// ---------------- host ----------------
static float* symaddrf(const void* sym) {
    void* p = nullptr;
    cudaGetSymbolAddress(&p, sym);
    return (float*)p;
}
static __half* symaddrh(const void* sym) {
    void* p = nullptr;
    cudaGetSymbolAddress(&p, sym);
    return (__half*)p;
}

extern "C" void kernel_launch(void* const* d_in, const int* in_sizes, int n_in,
                              void* d_out, int out_size) {
    const float* x      = (const float*)d_in[0];
    const float* tf     = (const float*)d_in[1];
    const float* Wp     = (const float*)d_in[2];
    const float* bp     = (const float*)d_in[3];
    const float* ln_g   = (const float*)d_in[4];
    const float* ln_b   = (const float*)d_in[5];
    const float* Wup    = (const float*)d_in[6];
    const float* bup    = (const float*)d_in[7];
    const float* conv_w = (const float*)d_in[8];
    const float* conv_b = (const float*)d_in[9];
    const float* Wq     = (const float*)d_in[10];
    const float* Wk     = (const float*)d_in[11];
    const float* Wv     = (const float*)d_in[12];
    const float* Wif    = (const float*)d_in[13];
    const float* bif    = (const float*)d_in[14];
    const float* gn_g   = (const float*)d_in[15];
    const float* gn_b   = (const float*)d_in[16];
    const float* skip   = (const float*)d_in[17];
    const float* Wdown  = (const float*)d_in[18];
    const float* bdown  = (const float*)d_in[19];
    const float* lnf_g  = (const float*)d_in[20];
    const float* lnf_b  = (const float*)d_in[21];
    const float* Wf     = (const float*)d_in[22];
    const float* bf     = (const float*)d_in[23];
    float* out = (float*)d_out;

    float* p_h   = symaddrf(g_h);
    float* p_up  = symaddrf(g_up);
    float* p_wc  = symaddrf(g_wc);
    __half* p_hn_h = symaddrh(g_hn_h);
    __half* p_hn_l = symaddrh(g_hn_l);
    __half* p_xc_h = symaddrh(g_xc_h);
    __half* p_xc_l = symaddrh(g_xc_l);
    __half* p_xm_h = symaddrh(g_xm_h);
    __half* p_xm_l = symaddrh(g_xm_l);
    __half* p_mix_h = symaddrh(g_mix_h);
    __half* p_mix_l = symaddrh(g_mix_l);
    __half* p_wt_h = symaddrh(g_wt_h);
    __half* p_qh = symaddrh(g_qh);
    __half* p_ql = symaddrh(g_ql);
    __half* p_kh = symaddrh(g_kh);
    __half* p_vh = symaddrh(g_vh);

    cudaFuncSetAttribute(attn2_kernel, cudaFuncAttributeMaxDynamicSharedMemorySize, ATTN2_SMEM);
    cudaFuncSetAttribute(mmagemm2_kernel<0>, cudaFuncAttributeMaxDynamicSharedMemorySize, GEMM_SMEM);
    cudaFuncSetAttribute(mmagemm2_kernel<1>, cudaFuncAttributeMaxDynamicSharedMemorySize, GEMM_SMEM);
    cudaFuncSetAttribute(mmagemm2_kernel<2>, cudaFuncAttributeMaxDynamicSharedMemorySize, GEMM_SMEM);
    cudaFuncSetAttribute(mmagemm2_kernel<3>, cudaFuncAttributeMaxDynamicSharedMemorySize, GEMM_SMEM);

    // weight prep (batched over layers)
    dim3 wblk(32, 8);
    wsplit_all<<<dim3(D/32, 2*DI/32, NL), wblk>>>(Wup, (long)D*2*DI, D, 2*DI,
                                                  p_wt_h + WT_UP_OFF, WT_L);
    wsplit_all<<<dim3(DI/32, DI/32, NL), wblk>>>(Wq, (long)DI*DI, DI, DI,
                                                 p_wt_h + WT_Q_OFF, WT_L);
    wsplit_all<<<dim3(DI/32, DI/32, NL), wblk>>>(Wk, (long)DI*DI, DI, DI,
                                                 p_wt_h + WT_K_OFF, WT_L);
    wsplit_all<<<dim3(DI/32, DI/32, NL), wblk>>>(Wv, (long)DI*DI, DI, DI,
                                                 p_wt_h + WT_V_OFF, WT_L);
    wsplit_all<<<dim3(DI/32, D/32, NL), wblk>>>(Wdown, (long)DI*D, DI, D,
                                                p_wt_h + WT_DN_OFF, WT_L);
    wcomb_kernel<<<dim3(DI, NL), 256>>>(Wq, Wk, Wv, Wif, p_wc);

    embed_kernel<<<NT, 256>>>(x, tf, Wp, bp);

    for (int l = 0; l < NL; l++) {
        size_t wo = (size_t)l * WT_L;
        ln256_kernel<<<NT, 256>>>(p_h, ln_g + l*D, ln_b + l*D);

        mmagemm2_kernel<2><<<dim3(NT/128, 1024/128), 256, GEMM_SMEM>>>(
            p_hn_h, p_hn_l, D, p_wt_h + wo + WT_UP_OFF,
            bup + l*2*DI, nullptr, p_up, 2*DI, p_xm_h, p_xm_l, DI, D);

        conv_kernel<<<NT*DI/256, 256>>>(conv_w + l*KC*DI, conv_b + l*DI);

        mmagemm2_kernel<1><<<dim3(NT/128, DI/128), 256, GEMM_SMEM>>>(
            p_xc_h, p_xc_l, DI, p_wt_h + wo + WT_Q_OFF,
            nullptr, nullptr, nullptr, 0, p_qh, p_ql, DI, DI);
        mmagemm2_kernel<3><<<dim3(NT/128, DI/128), 256, GEMM_SMEM>>>(
            p_xc_h, p_xc_l, DI, p_wt_h + wo + WT_K_OFF,
            nullptr, nullptr, nullptr, 0, p_kh, nullptr, DI, DI);
        mmagemm2_kernel<3><<<dim3(NT/128, DI/128), 256, GEMM_SMEM>>>(
            p_xm_h, p_xm_l, DI, p_wt_h + wo + WT_V_OFF,
            nullptr, nullptr, nullptr, 0, p_vh, nullptr, DI, DI);

        gates2_kernel<<<NT/8, 256>>>(p_wc + (size_t)l*DI*16, bif + l*2*NH);
        gatescan_kernel<<<NBH, 32>>>();

        attn2_kernel<<<dim3(SS/128, NBH), 256, ATTN2_SMEM>>>();

        gnmerge_kernel<<<NT, 512>>>(gn_g + l*DI, gn_b + l*DI, skip + l*DI);

        mmagemm2_kernel<0><<<dim3(NT/128, D/128), 256, GEMM_SMEM>>>(
            p_mix_h, p_mix_l, DI, p_wt_h + wo + WT_DN_OFF,
            bdown + l*D, p_h, p_h, D, nullptr, nullptr, 0, DI);
    }

    final_kernel<<<NB, 256>>>(lnf_g, lnf_b, Wf, bf, out);
}

// round 7
// speedup vs baseline: 6.1534x; 1.0959x over previous
#include <cuda_runtime.h>
#include <cuda_fp16.h>
#include <math.h>
#include <stdint.h>

#define D   256
#define DI  512
#define NH  4
#define DH  128
#define NL  4
#define KC  4
#define NB  8
#define SS  1024
#define NT  (NB*SS)
#define NBH (NB*NH)

// ---------------- scratch ----------------
__device__ float g_h [NT*D];
__device__ float g_up[NT*2*DI];
__device__ float g_xc[NT*DI];
__device__ float g_htp[2*NT*DI];     // unnormalized attention partials
__device__ float g_rs [2*NBH*SS];    // partial row sums
__device__ float g_gates[NT*2*NH];
__device__ float g_alpha[NBH*SS];
__device__ float g_beta [NBH*SS];
__device__ float g_m    [NBH*SS];
__device__ float g_wc   [NL*DI*16];

__device__ __half g_hn_h[NT*D],  g_hn_l[NT*D];
__device__ __half g_xc_h[NT*DI], g_xc_l[NT*DI];
__device__ __half g_xm_h[NT*DI], g_xm_l[NT*DI];
__device__ __half g_mix_h[NT*DI], g_mix_l[NT*DI];
__device__ __half g_qh[NT*DI], g_ql[NT*DI];
__device__ __half g_kh[NT*DI];
__device__ __half g_vh[NT*DI];

#define WT_UP_OFF   0
#define WT_Q_OFF    262144
#define WT_K_OFF    524288
#define WT_V_OFF    786432
#define WT_DN_OFF   1048576
#define WT_L        1179648
__device__ __half g_wt_h[NL*WT_L];

__device__ __forceinline__ uint32_t smem_u32(const void* p) {
    uint32_t a;
    asm("{ .reg .u64 t; cvta.to.shared.u64 t, %1; cvt.u32.u64 %0, t; }" : "=r"(a) : "l"(p));
    return a;
}
__device__ __forceinline__ void ldmx4(uint32_t* r, uint32_t addr) {
    asm volatile("ldmatrix.sync.aligned.m8n8.x4.shared.b16 {%0,%1,%2,%3}, [%4];"
        : "=r"(r[0]), "=r"(r[1]), "=r"(r[2]), "=r"(r[3]) : "r"(addr));
}
__device__ __forceinline__ void mma16816(float* d, const uint32_t* a, const uint32_t* b) {
    asm volatile(
        "mma.sync.aligned.m16n8k16.row.col.f32.f16.f16.f32 "
        "{%0,%1,%2,%3}, {%4,%5,%6,%7}, {%8,%9}, {%0,%1,%2,%3};"
        : "+f"(d[0]), "+f"(d[1]), "+f"(d[2]), "+f"(d[3])
        : "r"(a[0]), "r"(a[1]), "r"(a[2]), "r"(a[3]), "r"(b[0]), "r"(b[1]));
}
__device__ __forceinline__ uint32_t packh2(float lo, float hi) {
    __half2 p = __floats2half2_rn(lo, hi);
    return *(uint32_t*)&p;
}
__device__ __forceinline__ void cpa16(uint32_t s, const void* g) {
    asm volatile("cp.async.cg.shared.global [%0], [%1], 16;" :: "r"(s), "l"(g));
}
#define CP_COMMIT() asm volatile("cp.async.commit_group;" ::: "memory")
#define CP_WAIT0()  asm volatile("cp.async.wait_group 0;" ::: "memory")

// ---------------- embed ----------------
__global__ void embed_kernel(const float* __restrict__ x, const float* __restrict__ tf,
                             const float* __restrict__ Wp, const float* __restrict__ bp) {
    int t = blockIdx.x, d = threadIdx.x;
    float acc = bp[d] + x[t] * Wp[d];
#pragma unroll
    for (int j = 0; j < 4; j++) acc += tf[t*4 + j] * Wp[(1+j)*D + d];
    g_h[t*D + d] = acc;
}

// ---------------- LayerNorm D=256 -> fp16 hi/lo ----------------
__global__ void ln256_kernel(const float* __restrict__ in, const float* __restrict__ g,
                             const float* __restrict__ b) {
    int t = blockIdx.x, tid = threadIdx.x;
    __shared__ float red[256];
    float v = in[t*256 + tid];
    red[tid] = v; __syncthreads();
    for (int off = 128; off > 0; off >>= 1) { if (tid < off) red[tid] += red[tid+off]; __syncthreads(); }
    float mean = red[0] * (1.f/256.f); __syncthreads();
    float c = v - mean;
    red[tid] = c*c; __syncthreads();
    for (int off = 128; off > 0; off >>= 1) { if (tid < off) red[tid] += red[tid+off]; __syncthreads(); }
    float var = red[0] * (1.f/256.f);
    float y = c * rsqrtf(var + 1e-5f) * g[tid] + b[tid];
    __half h = __float2half_rn(y);
    g_hn_h[t*256 + tid] = h;
    g_hn_l[t*256 + tid] = __float2half_rn(y - __half2float(h));
}

// ---------------- batched weight transpose ----------------
__global__ void wsplit_all(const float* __restrict__ Wbase, long wstride, int K, int N,
                           __half* __restrict__ th, long ostride) {
    __shared__ float tile[32][33];
    int l = blockIdx.z;
    const float* W = Wbase + (size_t)l*wstride;
    __half* out = th + (size_t)l*ostride;
    int k0 = blockIdx.x*32, n0 = blockIdx.y*32;
    int tx = threadIdx.x, ty = threadIdx.y;
    for (int i = ty; i < 32; i += 8)
        tile[i][tx] = W[(size_t)(k0+i)*N + n0 + tx];
    __syncthreads();
    for (int i = ty; i < 32; i += 8)
        out[(size_t)(n0+i)*K + k0 + tx] = __float2half_rn(tile[tx][i]);
}

// ---------------- combined gate weights ----------------
__global__ void wcomb_kernel(const float* __restrict__ Wq0, const float* __restrict__ Wk0,
                             const float* __restrict__ Wv0, const float* __restrict__ Wif0,
                             float* __restrict__ wc0) {
    int i = blockIdx.x, l = blockIdx.y;
    const float* Wq = Wq0 + (size_t)l*DI*DI;
    const float* Wk = Wk0 + (size_t)l*DI*DI;
    const float* Wv = Wv0 + (size_t)l*DI*DI;
    const float* Wif = Wif0 + (size_t)l*3*DI*8;
    float* wc = wc0 + (size_t)l*DI*16;
    int warp = threadIdx.x >> 5, lane = threadIdx.x & 31;
    float a1 = 0.f, a2 = 0.f;
    for (int j = lane; j < DI; j += 32) {
        a1 += Wq[(size_t)i*DI + j] * Wif[j*8 + warp]
            + Wk[(size_t)i*DI + j] * Wif[(DI + j)*8 + warp];
        a2 += Wv[(size_t)i*DI + j] * Wif[(2*DI + j)*8 + warp];
    }
#pragma unroll
    for (int d = 16; d > 0; d >>= 1) {
        a1 += __shfl_xor_sync(0xFFFFFFFFu, a1, d);
        a2 += __shfl_xor_sync(0xFFFFFFFFu, a2, d);
    }
    if (lane == 0) {
        wc[i*16 + warp] = a1;
        wc[i*16 + 8 + warp] = a2;
    }
}

// ---------------- gates ----------------
__global__ void gates2_kernel(const float* __restrict__ wc, const float* __restrict__ bif) {
    int warp = threadIdx.x >> 5, lane = threadIdx.x & 31;
    int t = blockIdx.x*8 + warp;
    float acc[8];
#pragma unroll
    for (int g = 0; g < 8; g++) acc[g] = 0.f;
    const float* xcr = g_xc + (size_t)t*DI;
    const float* xmr = g_up + (size_t)t*2*DI;
    for (int j = lane; j < DI; j += 32) {
        float xcv = xcr[j], xmv = xmr[j];
        const float* w = wc + j*16;
#pragma unroll
        for (int g = 0; g < 8; g++) acc[g] += xcv*w[g] + xmv*w[8+g];
    }
#pragma unroll
    for (int g = 0; g < 8; g++) {
#pragma unroll
        for (int d = 16; d > 0; d >>= 1) acc[g] += __shfl_xor_sync(0xFFFFFFFFu, acc[g], d);
    }
    if (lane < 8) g_gates[(size_t)t*8 + lane] = acc[lane] + bif[lane];
}

// ================= shared GEMM machinery =================
#define TSTR 40
#define OFF_AH 0
#define OFF_AL 10240
#define OFF_BH 20480
#define STAGE_B 30720
#define GEMM_SMEM (2*STAGE_B)

struct GemmCtx {
    uint32_t aoff[2][2], boff[4][2];
    uint32_t soA, soB;
    int wm, wn, lane;
};
__device__ __forceinline__ void gemm_init(GemmCtx& c, int tid) {
    int warp = tid >> 5; c.lane = tid & 31;
    c.wm = warp >> 1; c.wn = warp & 1;
#pragma unroll
    for (int mt = 0; mt < 2; mt++)
#pragma unroll
        for (int ks = 0; ks < 2; ks++)
            c.aoff[mt][ks] = ((c.wm*32 + mt*16 + (c.lane & 15))*TSTR + ks*16 + ((c.lane >> 4) << 3))*2;
#pragma unroll
    for (int ntp = 0; ntp < 4; ntp++)
#pragma unroll
        for (int ks = 0; ks < 2; ks++)
            c.boff[ntp][ks] = ((c.wn*64 + ntp*16 + ((c.lane >> 4) << 3) + (c.lane & 7))*TSTR
                               + ks*16 + (((c.lane >> 3) & 1) << 3))*2;
    int ldRow = tid >> 2, ldQuad = tid & 3;
    c.soA = (ldRow*TSTR + ldQuad*8)*2;
    c.soB = ((ldRow+64)*TSTR + ldQuad*8)*2;
}
__device__ __forceinline__ void gemm_stage(const GemmCtx& c, uint32_t st, int tid,
                                           const __half* Ah0, const __half* Al0, int lda,
                                           const __half* Bh0, int K, int k0) {
    int ldRow = tid >> 2, ldQuad = tid & 3;
    cpa16(st + OFF_AH + c.soA, Ah0 + (size_t)ldRow*lda + k0 + ldQuad*8);
    cpa16(st + OFF_AL + c.soA, Al0 + (size_t)ldRow*lda + k0 + ldQuad*8);
    cpa16(st + OFF_BH + c.soA, Bh0 + (size_t)ldRow*K + k0 + ldQuad*8);
    cpa16(st + OFF_AH + c.soB, Ah0 + (size_t)(ldRow+64)*lda + k0 + ldQuad*8);
    cpa16(st + OFF_AL + c.soB, Al0 + (size_t)(ldRow+64)*lda + k0 + ldQuad*8);
    cpa16(st + OFF_BH + c.soB, Bh0 + (size_t)(ldRow+64)*K + k0 + ldQuad*8);
    CP_COMMIT();
}
__device__ __forceinline__ void gemm_math(const GemmCtx& c, uint32_t st, float acc[2][8][4]) {
    uint32_t sAh_b = st + OFF_AH, sAl_b = st + OFF_AL, sBh_b = st + OFF_BH;
#pragma unroll
    for (int ks = 0; ks < 2; ks++) {
        uint32_t ah[2][4], al[2][4], bh[4][4];
#pragma unroll
        for (int mt = 0; mt < 2; mt++) {
            ldmx4(ah[mt], sAh_b + c.aoff[mt][ks]);
            ldmx4(al[mt], sAl_b + c.aoff[mt][ks]);
        }
#pragma unroll
        for (int ntp = 0; ntp < 4; ntp++)
            ldmx4(bh[ntp], sBh_b + c.boff[ntp][ks]);
#pragma unroll
        for (int mt = 0; mt < 2; mt++)
#pragma unroll
            for (int nt = 0; nt < 8; nt++) {
                int p = nt >> 1, hh = (nt & 1) * 2;
                mma16816(acc[mt][nt], ah[mt], &bh[p][hh]);
                mma16816(acc[mt][nt], al[mt], &bh[p][hh]);
            }
    }
}

// MODE: 0 fp32 (+bias,+resid) | 2 fp32 + hi/lo split for col<DI
template<int MODE>
__global__ void __launch_bounds__(256)
mmagemm2_kernel(const __half* __restrict__ Ah, const __half* __restrict__ Al, int lda,
                const __half* __restrict__ Bh,
                const float* __restrict__ bias, const float* __restrict__ resid,
                float* __restrict__ C, int ldc,
                __half* __restrict__ Ohi, __half* __restrict__ Olo, int ldo,
                int K) {
    extern __shared__ char dsm[];
    uint32_t sb = smem_u32(dsm);
    int tid = threadIdx.x;
    GemmCtx c; gemm_init(c, tid);
    int rowBase = blockIdx.x * 128;
    int colBase = blockIdx.y * 128;
    const __half* Ah0 = Ah + (size_t)rowBase*lda;
    const __half* Al0 = Al + (size_t)rowBase*lda;
    const __half* Bh0 = Bh + (size_t)colBase*K;

    float acc[2][8][4];
#pragma unroll
    for (int mt = 0; mt < 2; mt++)
#pragma unroll
        for (int nt = 0; nt < 8; nt++)
#pragma unroll
            for (int i = 0; i < 4; i++) acc[mt][nt][i] = 0.f;

    int nch = K >> 5;
    gemm_stage(c, sb, tid, Ah0, Al0, lda, Bh0, K, 0);
    int buf = 0;
    for (int ch = 0; ch < nch; ch++) {
        CP_WAIT0();
        __syncthreads();
        if (ch + 1 < nch)
            gemm_stage(c, sb + (buf^1)*STAGE_B, tid, Ah0, Al0, lda, Bh0, K, (ch+1) << 5);
        gemm_math(c, sb + buf*STAGE_B, acc);
        buf ^= 1;
        __syncthreads();
    }

    int r0b = rowBase + c.wm*32 + (c.lane >> 2);
    int cb  = colBase + c.wn*64 + (c.lane & 3)*2;
#pragma unroll
    for (int mt = 0; mt < 2; mt++) {
#pragma unroll
        for (int nt = 0; nt < 8; nt++) {
            int col = cb + nt*8;
#pragma unroll
            for (int half = 0; half < 2; half++) {
                int row = r0b + mt*16 + half*8;
                float vx = acc[mt][nt][half*2+0];
                float vy = acc[mt][nt][half*2+1];
                if (bias) { vx += bias[col]; vy += bias[col+1]; }
                if (MODE == 0 && resid) {
                    const float2 r2 = *(const float2*)(resid + (size_t)row*ldc + col);
                    vx += r2.x; vy += r2.y;
                }
                float2 o; o.x = vx; o.y = vy;
                *(float2*)(C + (size_t)row*ldc + col) = o;
                if (MODE == 2 && col < DI) {
                    __half hx = __float2half_rn(vx);
                    __half hy = __float2half_rn(vy);
                    __half2 hv; hv.x = hx; hv.y = hy;
                    __half2 lv;
                    lv.x = __float2half_rn(vx - __half2float(hx));
                    lv.y = __float2half_rn(vy - __half2float(hy));
                    *(__half2*)(Ohi + (size_t)row*ldo + col) = hv;
                    *(__half2*)(Olo + (size_t)row*ldo + col) = lv;
                }
            }
        }
    }
}

// ---------------- fused Q/K/V GEMM: grid (NT/128, 12) ----------------
__global__ void __launch_bounds__(256)
qkvgemm_kernel(const __half* __restrict__ wt) {
    extern __shared__ char dsm[];
    uint32_t sb = smem_u32(dsm);
    int tid = threadIdx.x;
    GemmCtx c; gemm_init(c, tid);
    int rowBase = blockIdx.x * 128;
    int yb = blockIdx.y;
    int sel = yb >> 2;              // 0=Q 1=K 2=V
    int colBase = (yb & 3) * 128;

    const __half* Ah = (sel == 2) ? g_xm_h : g_xc_h;
    const __half* Al = (sel == 2) ? g_xm_l : g_xc_l;
    const __half* Bh0 = wt + (sel == 0 ? WT_Q_OFF : sel == 1 ? WT_K_OFF : WT_V_OFF)
                      + (size_t)colBase*DI;
    const __half* Ah0 = Ah + (size_t)rowBase*DI;
    const __half* Al0 = Al + (size_t)rowBase*DI;

    float acc[2][8][4];
#pragma unroll
    for (int mt = 0; mt < 2; mt++)
#pragma unroll
        for (int nt = 0; nt < 8; nt++)
#pragma unroll
            for (int i = 0; i < 4; i++) acc[mt][nt][i] = 0.f;

    gemm_stage(c, sb, tid, Ah0, Al0, DI, Bh0, DI, 0);
    int buf = 0;
    for (int ch = 0; ch < 16; ch++) {
        CP_WAIT0();
        __syncthreads();
        if (ch + 1 < 16)
            gemm_stage(c, sb + (buf^1)*STAGE_B, tid, Ah0, Al0, DI, Bh0, DI, (ch+1) << 5);
        gemm_math(c, sb + buf*STAGE_B, acc);
        buf ^= 1;
        __syncthreads();
    }

    __half* Ohi = (sel == 0) ? g_qh : (sel == 1) ? g_kh : g_vh;
    int r0b = rowBase + c.wm*32 + (c.lane >> 2);
    int cb  = colBase + c.wn*64 + (c.lane & 3)*2;
#pragma unroll
    for (int mt = 0; mt < 2; mt++) {
#pragma unroll
        for (int nt = 0; nt < 8; nt++) {
            int col = cb + nt*8;
#pragma unroll
            for (int half = 0; half < 2; half++) {
                int row = r0b + mt*16 + half*8;
                float vx = acc[mt][nt][half*2+0];
                float vy = acc[mt][nt][half*2+1];
                __half hx = __float2half_rn(vx);
                __half hy = __float2half_rn(vy);
                __half2 hv; hv.x = hx; hv.y = hy;
                *(__half2*)(Ohi + (size_t)row*DI + col) = hv;
                if (sel == 0) {
                    __half2 lv;
                    lv.x = __float2half_rn(vx - __half2float(hx));
                    lv.y = __float2half_rn(vy - __half2float(hy));
                    *(__half2*)(g_ql + (size_t)row*DI + col) = lv;
                }
            }
        }
    }
}

// ---------------- conv + SiLU ----------------
__global__ void conv_kernel(const float* __restrict__ w, const float* __restrict__ bias) {
    int idx = blockIdx.x * blockDim.x + threadIdx.x;
    int c = idx % DI;
    int t = idx / DI;
    int s = t % SS;
    float acc = bias[c];
#pragma unroll
    for (int j = 0; j < KC; j++) {
        int ss = s - 3 + j;
        if (ss >= 0) acc += g_up[(size_t)(t - 3 + j)*2*DI + c] * w[j*DI + c];
    }
    float y = acc / (1.f + __expf(-acc));
    g_xc[idx] = y;
    __half h = __float2half_rn(y);
    g_xc_h[idx] = h;
    g_xc_l[idx] = __float2half_rn(y - __half2float(h));
}

// ---------------- gate scan ----------------
__global__ void gatescan_kernel() {
    int bh = blockIdx.x;
    int lane = threadIdx.x;
    int b = bh >> 2, h = bh & 3;
    float carryF = 0.f, carryM = -1e30f;
    for (int c = 0; c < SS/32; c++) {
        int t = c*32 + lane;
        const float* gp = g_gates + (size_t)(b*SS + t)*8;
        float fp = gp[NH + h], ipv = gp[h];
        float lf = (fp >= 0.f) ? -log1pf(__expf(-fp)) : fp - log1pf(__expf(fp));
        float s = lf;
#pragma unroll
        for (int d = 1; d < 32; d <<= 1) {
            float v = __shfl_up_sync(0xFFFFFFFFu, s, d);
            if (lane >= d) s += v;
        }
        float Fc = carryF + s;
        float bt = ipv - Fc;
        float mx = bt;
#pragma unroll
        for (int d = 1; d < 32; d <<= 1) {
            float v = __shfl_up_sync(0xFFFFFFFFu, mx, d);
            if (lane >= d) mx = fmaxf(mx, v);
        }
        float rmax = fmaxf(carryM, mx);
        g_beta [bh*SS + t] = bt;
        g_alpha[bh*SS + t] = -rmax;
        g_m    [bh*SS + t] = Fc + rmax;
        carryF += __shfl_sync(0xFFFFFFFFu, s, 31);
        carryM  = fmaxf(carryM, __shfl_sync(0xFFFFFFFFu, rmax, 31));
    }
}

// ================= split-s fp16 attention: grid (8, 2, 32) =================
#define STRQ 136
#define STRV 40
#define A2_QH 0
#define A2_QL (A2_QH + 128*STRQ*2)
#define A2_KH (A2_QL + 128*STRQ*2)
#define A2_VH (A2_KH + 32*STRQ*2)
#define A2_BT (A2_VH + 128*STRV*2)
#define ATTN2_SMEM (A2_BT + 32*4)
#define SCALE 0.08838834764831845f

__global__ void __launch_bounds__(256) attn2_kernel() {
    extern __shared__ char sm2[];
    __half* Qh = (__half*)(sm2 + A2_QH);
    __half* Ql = (__half*)(sm2 + A2_QL);
    __half* Kh = (__half*)(sm2 + A2_KH);
    __half* Vh = (__half*)(sm2 + A2_VH);
    float* bts = (float*)(sm2 + A2_BT);

    int qt = blockIdx.x, sh = blockIdx.y, bh = blockIdx.z;
    int b = bh >> 2, h = bh & 3;
    int tid = threadIdx.x, warp = tid >> 5, lane = tid & 31;
    int t0 = qt * 128;

#pragma unroll
    for (int j = 0; j < 8; j++) {
        int i = tid + j*256;
        int row = i >> 4, c8 = (i & 15)*8;
        size_t gb = (size_t)(b*SS + t0 + row)*DI + h*DH + c8;
        *(uint4*)(Qh + row*STRQ + c8) = *(const uint4*)(g_qh + gb);
        *(uint4*)(Ql + row*STRQ + c8) = *(const uint4*)(g_ql + gb);
    }

    int tr0 = t0 + warp*16 + (lane >> 2);
    int tr1 = tr0 + 8;
    float al0 = g_alpha[bh*SS + tr0];
    float al1 = g_alpha[bh*SS + tr1];

    float O[16][4];
#pragma unroll
    for (int nt = 0; nt < 16; nt++)
#pragma unroll
        for (int i = 0; i < 4; i++) O[nt][i] = 0.f;
    float rs0 = 0.f, rs1 = 0.f;

    uint32_t sQh = smem_u32(Qh), sQl = smem_u32(Ql);
    uint32_t sKh = smem_u32(Kh), sVh = smem_u32(Vh);

    uint32_t qoff[8], koff[2][8], voff[8][2];
#pragma unroll
    for (int ks = 0; ks < 8; ks++)
        qoff[ks] = ((warp*16 + (lane & 15))*STRQ + ks*16 + ((lane >> 4) << 3))*2;
#pragma unroll
    for (int np = 0; np < 2; np++)
#pragma unroll
        for (int ks = 0; ks < 8; ks++)
            koff[np][ks] = ((np*16 + ((lane >> 4) << 3) + (lane & 7))*STRQ
                            + ks*16 + (((lane >> 3) & 1) << 3))*2;
#pragma unroll
    for (int np = 0; np < 8; np++)
#pragma unroll
        for (int kv = 0; kv < 2; kv++)
            voff[np][kv] = ((np*16 + ((lane >> 4) << 3) + (lane & 7))*STRV
                            + kv*16 + (((lane >> 3) & 1) << 3))*2;

    int half_tiles = 2*(qt + 1);
    int st_lo = sh * half_tiles;
    int st_hi = st_lo + half_tiles;
    for (int st = st_lo; st < st_hi; st++) {
        int s0 = st * 32;
        __syncthreads();
#pragma unroll
        for (int j = 0; j < 2; j++) {
            int i = tid + j*256;
            int row = i >> 4, c8 = (i & 15)*8;
            size_t gb = (size_t)(b*SS + s0 + row)*DI + h*DH + c8;
            *(uint4*)(Kh + row*STRQ + c8) = *(const uint4*)(g_kh + gb);
            uint4 vh4 = *(const uint4*)(g_vh + gb);
            const __half* vhp = (const __half*)&vh4;
#pragma unroll
            for (int e = 0; e < 8; e++)
                Vh[(c8+e)*STRV + row] = vhp[e];
        }
        if (tid < 32) bts[tid] = g_beta[bh*SS + s0 + tid];
        __syncthreads();

        float S[4][4];
#pragma unroll
        for (int nt = 0; nt < 4; nt++)
#pragma unroll
            for (int i = 0; i < 4; i++) S[nt][i] = 0.f;
#pragma unroll
        for (int ks = 0; ks < 8; ks++) {
            uint32_t ah[4], al[4], bkh[2][4];
            ldmx4(ah, sQh + qoff[ks]);
            ldmx4(al, sQl + qoff[ks]);
            ldmx4(bkh[0], sKh + koff[0][ks]);
            ldmx4(bkh[1], sKh + koff[1][ks]);
#pragma unroll
            for (int nt = 0; nt < 4; nt++) {
                int p = nt >> 1, hh = (nt & 1)*2;
                mma16816(S[nt], ah, &bkh[p][hh]);
                mma16816(S[nt], al, &bkh[p][hh]);
            }
        }

        uint32_t Ph[2][4], Pl[2][4];
#pragma unroll
        for (int nt = 0; nt < 4; nt++) {
            float pv[4], plv[4];
#pragma unroll
            for (int r = 0; r < 4; r++) {
                int trow = (r < 2) ? tr0 : tr1;
                float alv = (r < 2) ? al0 : al1;
                int cl = nt*8 + (lane & 3)*2 + (r & 1);
                int sc = s0 + cl;
                float w = (sc <= trow) ? __expf(alv + bts[cl]) : 0.f;
                float p = S[nt][r] * SCALE * w;
                if (r < 2) rs0 += p; else rs1 += p;
                pv[r] = p;
                float ph = __half2float(__float2half_rn(p));
                plv[r] = p - ph;
            }
            int kv = nt >> 1;
            if ((nt & 1) == 0) {
                Ph[kv][0] = packh2(pv[0], pv[1]);
                Ph[kv][1] = packh2(pv[2], pv[3]);
                Pl[kv][0] = packh2(plv[0], plv[1]);
                Pl[kv][1] = packh2(plv[2], plv[3]);
            } else {
                Ph[kv][2] = packh2(pv[0], pv[1]);
                Ph[kv][3] = packh2(pv[2], pv[3]);
                Pl[kv][2] = packh2(plv[0], plv[1]);
                Pl[kv][3] = packh2(plv[2], plv[3]);
            }
        }

#pragma unroll
        for (int kv = 0; kv < 2; kv++) {
#pragma unroll
            for (int np = 0; np < 8; np++) {
                uint32_t bvh[4];
                ldmx4(bvh, sVh + voff[np][kv]);
#pragma unroll
                for (int hh = 0; hh < 2; hh++) {
                    int nt = np*2 + hh;
                    mma16816(O[nt], Ph[kv], &bvh[hh*2]);
                    mma16816(O[nt], Pl[kv], &bvh[hh*2]);
                }
            }
        }
    }

    rs0 += __shfl_xor_sync(0xFFFFFFFFu, rs0, 1);
    rs0 += __shfl_xor_sync(0xFFFFFFFFu, rs0, 2);
    rs1 += __shfl_xor_sync(0xFFFFFFFFu, rs1, 1);
    rs1 += __shfl_xor_sync(0xFFFFFFFFu, rs1, 2);
    if ((lane & 3) == 0) {
        g_rs[sh*NBH*SS + bh*SS + tr0] = rs0;
        g_rs[sh*NBH*SS + bh*SS + tr1] = rs1;
    }

    float* o0 = g_htp + (size_t)sh*NT*DI + (size_t)(b*SS + tr0)*DI + h*DH + (lane & 3)*2;
    float* o1 = g_htp + (size_t)sh*NT*DI + (size_t)(b*SS + tr1)*DI + h*DH + (lane & 3)*2;
#pragma unroll
    for (int nt = 0; nt < 16; nt++) {
        float2 v0; v0.x = O[nt][0]; v0.y = O[nt][1];
        float2 v1; v1.x = O[nt][2]; v1.y = O[nt][3];
        *(float2*)(o0 + nt*8) = v0;
        *(float2*)(o1 + nt*8) = v1;
    }
}

// ---------------- combine partials + per-head LN + skip + SiLU gate ----------------
__global__ void gnmerge_kernel(const float* __restrict__ gn_g, const float* __restrict__ gn_b,
                               const float* __restrict__ skip) {
    int t = blockIdx.x, tid = threadIdx.x;
    __shared__ float red[512];
    int l = tid & 127;
    int gbase = (tid >> 7) << 7;
    int b = t >> 10, s = t & 1023;
    int h = tid >> 7;
    int bh = b*NH + h;
    float rs = g_rs[bh*SS + s] + g_rs[NBH*SS + bh*SS + s];
    float me = __expf(-g_m[bh*SS + s]);
    float inv = 1.f / (fmaxf(fabsf(rs), me) + 1e-6f);
    float v = (g_htp[(size_t)t*DI + tid] + g_htp[(size_t)NT*DI + (size_t)t*DI + tid]) * inv;
    red[tid] = v; __syncthreads();
    for (int off = 64; off > 0; off >>= 1) { if (l < off) red[tid] += red[tid+off]; __syncthreads(); }
    float mean = red[gbase] * (1.f/128.f); __syncthreads();
    float c = v - mean;
    red[tid] = c*c; __syncthreads();
    for (int off = 64; off > 0; off >>= 1) { if (l < off) red[tid] += red[tid+off]; __syncthreads(); }
    float var = red[gbase] * (1.f/128.f);
    float y = c * rsqrtf(var + 1e-5f) * gn_g[tid] + gn_b[tid];
    y += skip[tid] * g_xc[(size_t)t*DI + tid];
    float z = g_up[(size_t)t*2*DI + DI + tid];
    y *= z / (1.f + __expf(-z));
    __half hh = __float2half_rn(y);
    g_mix_h[(size_t)t*DI + tid] = hh;
    g_mix_l[(size_t)t*DI + tid] = __float2half_rn(y - __half2float(hh));
}

// ---------------- final LN + projection ----------------
__global__ void final_kernel(const float* __restrict__ lnf_g, const float* __restrict__ lnf_b,
                             const float* __restrict__ Wf, const float* __restrict__ bf,
                             float* __restrict__ out) {
    int b = blockIdx.x, tid = threadIdx.x;
    __shared__ float red[256];
    float v = g_h[(size_t)(b*SS + SS - 1)*D + tid];
    red[tid] = v; __syncthreads();
    for (int off = 128; off > 0; off >>= 1) { if (tid < off) red[tid] += red[tid+off]; __syncthreads(); }
    float mean = red[0] * (1.f/256.f); __syncthreads();
    float c = v - mean;
    red[tid] = c*c; __syncthreads();
    for (int off = 128; off > 0; off >>= 1) { if (tid < off) red[tid] += red[tid+off]; __syncthreads(); }
    float var = red[0] * (1.f/256.f); __syncthreads();
    float y = c * rsqrtf(var + 1e-5f) * lnf_g[tid] + lnf_b[tid];
    red[tid] = y * Wf[tid]; __syncthreads();
    for (int off = 128; off > 0; off >>= 1) { if (tid < off) red[tid] += red[tid+off]; __syncthreads(); }
    if (tid == 0) out[b] = red[0] + bf[0];
}

// ---------------- host ----------------
static float* symaddrf(const void* sym) {
    void* p = nullptr;
    cudaGetSymbolAddress(&p, sym);
    return (float*)p;
}
static __half* symaddrh(const void* sym) {
    void* p = nullptr;
    cudaGetSymbolAddress(&p, sym);
    return (__half*)p;
}

extern "C" void kernel_launch(void* const* d_in, const int* in_sizes, int n_in,
                              void* d_out, int out_size) {
    const float* x      = (const float*)d_in[0];
    const float* tf     = (const float*)d_in[1];
    const float* Wp     = (const float*)d_in[2];
    const float* bp     = (const float*)d_in[3];
    const float* ln_g   = (const float*)d_in[4];
    const float* ln_b   = (const float*)d_in[5];
    const float* Wup    = (const float*)d_in[6];
    const float* bup    = (const float*)d_in[7];
    const float* conv_w = (const float*)d_in[8];
    const float* conv_b = (const float*)d_in[9];
    const float* Wq     = (const float*)d_in[10];
    const float* Wk     = (const float*)d_in[11];
    const float* Wv     = (const float*)d_in[12];
    const float* Wif    = (const float*)d_in[13];
    const float* bif    = (const float*)d_in[14];
    const float* gn_g   = (const float*)d_in[15];
    const float* gn_b   = (const float*)d_in[16];
    const float* skip   = (const float*)d_in[17];
    const float* Wdown  = (const float*)d_in[18];
    const float* bdown  = (const float*)d_in[19];
    const float* lnf_g  = (const float*)d_in[20];
    const float* lnf_b  = (const float*)d_in[21];
    const float* Wf     = (const float*)d_in[22];
    const float* bf     = (const float*)d_in[23];
    float* out = (float*)d_out;

    float* p_h   = symaddrf(g_h);
    float* p_up  = symaddrf(g_up);
    float* p_wc  = symaddrf(g_wc);
    __half* p_hn_h = symaddrh(g_hn_h);
    __half* p_hn_l = symaddrh(g_hn_l);
    __half* p_xm_h = symaddrh(g_xm_h);
    __half* p_xm_l = symaddrh(g_xm_l);
    __half* p_mix_h = symaddrh(g_mix_h);
    __half* p_mix_l = symaddrh(g_mix_l);
    __half* p_wt_h = symaddrh(g_wt_h);

    cudaFuncSetAttribute(attn2_kernel, cudaFuncAttributeMaxDynamicSharedMemorySize, ATTN2_SMEM);
    cudaFuncSetAttribute(mmagemm2_kernel<0>, cudaFuncAttributeMaxDynamicSharedMemorySize, GEMM_SMEM);
    cudaFuncSetAttribute(mmagemm2_kernel<2>, cudaFuncAttributeMaxDynamicSharedMemorySize, GEMM_SMEM);
    cudaFuncSetAttribute(qkvgemm_kernel, cudaFuncAttributeMaxDynamicSharedMemorySize, GEMM_SMEM);

    dim3 wblk(32, 8);
    wsplit_all<<<dim3(D/32, 2*DI/32, NL), wblk>>>(Wup, (long)D*2*DI, D, 2*DI,
                                                  p_wt_h + WT_UP_OFF, WT_L);
    wsplit_all<<<dim3(DI/32, DI/32, NL), wblk>>>(Wq, (long)DI*DI, DI, DI,
                                                 p_wt_h + WT_Q_OFF, WT_L);
    wsplit_all<<<dim3(DI/32, DI/32, NL), wblk>>>(Wk, (long)DI*DI, DI, DI,
                                                 p_wt_h + WT_K_OFF, WT_L);
    wsplit_all<<<dim3(DI/32, DI/32, NL), wblk>>>(Wv, (long)DI*DI, DI, DI,
                                                 p_wt_h + WT_V_OFF, WT_L);
    wsplit_all<<<dim3(DI/32, D/32, NL), wblk>>>(Wdown, (long)DI*D, DI, D,
                                                p_wt_h + WT_DN_OFF, WT_L);
    wcomb_kernel<<<dim3(DI, NL), 256>>>(Wq, Wk, Wv, Wif, p_wc);

    embed_kernel<<<NT, 256>>>(x, tf, Wp, bp);

    for (int l = 0; l < NL; l++) {
        size_t wo = (size_t)l * WT_L;
        ln256_kernel<<<NT, 256>>>(p_h, ln_g + l*D, ln_b + l*D);

        mmagemm2_kernel<2><<<dim3(NT/128, 1024/128), 256, GEMM_SMEM>>>(
            p_hn_h, p_hn_l, D, p_wt_h + wo + WT_UP_OFF,
            bup + l*2*DI, nullptr, p_up, 2*DI, p_xm_h, p_xm_l, DI, D);

        conv_kernel<<<NT*DI/256, 256>>>(conv_w + l*KC*DI, conv_b + l*DI);

        qkvgemm_kernel<<<dim3(NT/128, 12), 256, GEMM_SMEM>>>(p_wt_h + wo);

        gates2_kernel<<<NT/8, 256>>>(p_wc + (size_t)l*DI*16, bif + l*2*NH);
        gatescan_kernel<<<NBH, 32>>>();

        attn2_kernel<<<dim3(8, 2, NBH), 256, ATTN2_SMEM>>>();

        gnmerge_kernel<<<NT, 512>>>(gn_g + l*DI, gn_b + l*DI, skip + l*DI);

        mmagemm2_kernel<0><<<dim3(NT/128, D/128), 256, GEMM_SMEM>>>(
            p_mix_h, p_mix_l, DI, p_wt_h + wo + WT_DN_OFF,
            bdown + l*D, p_h, p_h, D, nullptr, nullptr, 0, DI);
    }

    final_kernel<<<NB, 256>>>(lnf_g, lnf_b, Wf, bf, out);
}